// round 12
// baseline (speedup 1.0000x reference)
#include <cuda_runtime.h>
#include <cuda_bf16.h>
#include <math.h>
#include <stdint.h>

// Problem constants
#define HIDDEN 2048
#define NHEAD  16
#define HDIM   128
#define BB     2
#define SSEQ   2048
#define BH     (BB * NHEAD)      // 32
#define MROWS  (BB * SSEQ)       // 4096
#define NSPLIT 2
#define KV_PER_SPLIT (SSEQ / NSPLIT)         // 1024
#define FA_ITERS (KV_PER_SPLIT / 32)         // 32

// ---------------- scratch (device globals; no allocation allowed) -----------
__device__ __align__(128) __nv_bfloat16 g_xh [(size_t)MROWS * HIDDEN];
__device__ __align__(128) __nv_bfloat16 g_xl [(size_t)MROWS * HIDDEN];
__device__ __align__(128) __nv_bfloat16 g_w3h[(size_t)3 * HIDDEN * HIDDEN];  // Wq|Wk|Wv
__device__ __align__(128) __nv_bfloat16 g_w3l[(size_t)3 * HIDDEN * HIDDEN];
__device__ __align__(128) __nv_bfloat16 g_woh[(size_t)HIDDEN * HIDDEN];
__device__ __align__(128) __nv_bfloat16 g_wol[(size_t)HIDDEN * HIDDEN];
__device__ __align__(128) float         g_b3 [3 * HIDDEN];                   // bq|bk|bv
__device__ __align__(128) __nv_bfloat16 g_qh [(size_t)BH * SSEQ * HDIM];  // [B,H,S,D]
__device__ __align__(128) __nv_bfloat16 g_ql [(size_t)BH * SSEQ * HDIM];
__device__ __align__(128) __nv_bfloat16 g_kh [(size_t)BH * SSEQ * HDIM];
__device__ __align__(128) __nv_bfloat16 g_kl [(size_t)BH * SSEQ * HDIM];
__device__ __align__(128) __nv_bfloat16 g_vh [(size_t)BH * SSEQ * HDIM];
__device__ __align__(128) __nv_bfloat16 g_vl [(size_t)BH * SSEQ * HDIM];
__device__ __align__(128) __nv_bfloat16 g_aoh[(size_t)MROWS * HIDDEN];
__device__ __align__(128) __nv_bfloat16 g_aol[(size_t)MROWS * HIDDEN];
__device__ __align__(128) float g_op[(size_t)NSPLIT * BH * SSEQ * HDIM];     // fp32 partial O
__device__ __align__(128) float g_ml[(size_t)NSPLIT * BH * SSEQ * 2];        // (m, l) per row

// ============================ PTX helpers ====================================
__device__ __forceinline__ uint32_t smem_to_u32(const void* smem_ptr) {
    uint32_t addr;
    asm("{ .reg .u64 tmp; cvta.to.shared.u64 tmp, %1; cvt.u32.u64 %0, tmp; }"
        : "=r"(addr) : "l"(smem_ptr));
    return addr;
}
#define CP_ASYNC16(smem_u32, gptr) \
    asm volatile("cp.async.cg.shared.global [%0], [%1], 16;" \
        :: "r"((uint32_t)(smem_u32)), "l"(gptr) : "memory")
#define CP_ASYNC_COMMIT() asm volatile("cp.async.commit_group;" ::: "memory")
#define CP_ASYNC_WAIT(n)  asm volatile("cp.async.wait_group %0;" :: "n"(n) : "memory")

__device__ __forceinline__ void ldsm4(uint32_t* r, uint32_t addr) {
    asm volatile("ldmatrix.sync.aligned.m8n8.x4.shared.b16 {%0,%1,%2,%3}, [%4];"
        : "=r"(r[0]), "=r"(r[1]), "=r"(r[2]), "=r"(r[3]) : "r"(addr));
}
__device__ __forceinline__ void ldsm4t(uint32_t* r, uint32_t addr) {
    asm volatile("ldmatrix.sync.aligned.m8n8.x4.trans.shared.b16 {%0,%1,%2,%3}, [%4];"
        : "=r"(r[0]), "=r"(r[1]), "=r"(r[2]), "=r"(r[3]) : "r"(addr));
}
__device__ __forceinline__ void mma16816(float* d, const uint32_t* a,
                                         uint32_t b0, uint32_t b1) {
    asm volatile(
        "mma.sync.aligned.m16n8k16.row.col.f32.bf16.bf16.f32 "
        "{%0,%1,%2,%3}, {%4,%5,%6,%7}, {%8,%9}, {%0,%1,%2,%3};"
        : "+f"(d[0]), "+f"(d[1]), "+f"(d[2]), "+f"(d[3])
        : "r"(a[0]), "r"(a[1]), "r"(a[2]), "r"(a[3]), "r"(b0), "r"(b1));
}
__device__ __forceinline__ float fast_exp2(float x) {
    float y;
    asm("ex2.approx.f32 %0, %1;" : "=f"(y) : "f"(x));
    return y;
}

// ===================== HMMA bf16x3 NT GEMM ==================================
// (unchanged: 128x128 CTA, K-chunk 32, XOR swizzle, 3-stage, 1 sync, 2 CTA/SM)
#define TG_TILE     (128 * 64)              // 8192
#define TG_STAGE    (4 * TG_TILE)           // Ah, Al, Bh, Bl = 32768
#define TG_SMEM     (3 * TG_STAGE)          // 98304 -> 2 CTAs/SM

__global__ void __launch_bounds__(256, 2)
tgemm_nt(const __nv_bfloat16* __restrict__ Ah, const __nv_bfloat16* __restrict__ Al,
         const __nv_bfloat16* __restrict__ Bh, const __nv_bfloat16* __restrict__ Bl,
         const float* __restrict__ bias, int K, int Ntot, int mode,
         float* __restrict__ outF,
         __nv_bfloat16* __restrict__ o0h, __nv_bfloat16* __restrict__ o0l,
         __nv_bfloat16* __restrict__ o1h, __nv_bfloat16* __restrict__ o1l,
         __nv_bfloat16* __restrict__ o2h, __nv_bfloat16* __restrict__ o2l)
{
    extern __shared__ __align__(128) char smem[];
    const uint32_t sb = smem_to_u32(smem);

    const int tid  = threadIdx.x;
    const int lane = tid & 31;
    const int wid  = tid >> 5;
    const int wm   = wid >> 2;
    const int wn   = wid & 3;

    const int m0 = blockIdx.y * 128;
    const int n0 = blockIdx.x * 128;
    const int nch = K >> 5;                  // K / 32

    const size_t aBase = (size_t)m0 * K;
    const size_t bBase = (size_t)n0 * K;

    float acc[4][4][4];
    #pragma unroll
    for (int i = 0; i < 4; i++)
        #pragma unroll
        for (int j = 0; j < 4; j++)
            #pragma unroll
            for (int t = 0; t < 4; t++) acc[i][j][t] = 0.0f;

    auto load_chunk = [&](int buf, int k0) {
        const uint32_t tb = sb + buf * TG_STAGE;
        #pragma unroll
        for (int ii = 0; ii < 2; ii++) {
            const int i = tid + ii * 256;        // 0..511
            const int r = i >> 2;                // row 0..127
            const int c = i & 3;                 // 16B chunk 0..3
            const uint32_t so = (uint32_t)(r * 64 + ((c ^ ((r >> 1) & 3)) << 4));
            const size_t aOff = aBase + (size_t)r * K + k0 + c * 8;
            const size_t bOff = bBase + (size_t)r * K + k0 + c * 8;
            CP_ASYNC16(tb + 0 * TG_TILE + so, (const char*)(Ah + aOff));
            CP_ASYNC16(tb + 1 * TG_TILE + so, (const char*)(Al + aOff));
            CP_ASYNC16(tb + 2 * TG_TILE + so, (const char*)(Bh + bOff));
            CP_ASYNC16(tb + 3 * TG_TILE + so, (const char*)(Bl + bOff));
        }
        CP_ASYNC_COMMIT();
    };

    const int hiA = lane >> 4;
    const int swA = ((lane & 15) >> 1) & 3;
    const uint32_t aRowOff = (uint32_t)((wm * 64 + (lane & 15)) * 64);
    const int hiB = (lane >> 3) & 1;
    const int swB = ((lane & 7) >> 1) & 3;
    const uint32_t bRowOff = (uint32_t)((wn * 32 + (lane & 7) + ((lane >> 4) & 1) * 8) * 64);

    load_chunk(0, 0);
    if (nch > 1) load_chunk(1, 32);

    for (int c = 0; c < nch; c++) {
        const int buf = c % 3;
        if (c + 1 < nch) { CP_ASYNC_WAIT(1); } else { CP_ASYNC_WAIT(0); }
        __syncthreads();
        if (c + 2 < nch) load_chunk((c + 2) % 3, (c + 2) * 32);

        const uint32_t tb  = sb + buf * TG_STAGE;
        const uint32_t tAh = tb + 0 * TG_TILE + aRowOff;
        const uint32_t tAl = tb + 1 * TG_TILE + aRowOff;
        const uint32_t tBh = tb + 2 * TG_TILE + bRowOff;
        const uint32_t tBl = tb + 3 * TG_TILE + bRowOff;

        #pragma unroll
        for (int ks = 0; ks < 2; ks++) {
            const uint32_t koA = (uint32_t)(((ks * 2 + hiA) ^ swA) << 4);
            const uint32_t koB = (uint32_t)(((ks * 2 + hiB) ^ swB) << 4);
            uint32_t a[4][4], bh[2][4], bl[2][4];
            #pragma unroll
            for (int mt = 0; mt < 4; mt++) ldsm4(a[mt], tAh + mt * (16 * 64) + koA);
            #pragma unroll
            for (int nt = 0; nt < 2; nt++) {
                ldsm4(bh[nt], tBh + nt * (16 * 64) + koB);
                ldsm4(bl[nt], tBl + nt * (16 * 64) + koB);
            }
            #pragma unroll
            for (int mi = 0; mi < 4; mi++)
                #pragma unroll
                for (int ni = 0; ni < 4; ni++) {
                    const int g = ni >> 1, o = (ni & 1) * 2;
                    mma16816(acc[mi][ni], a[mi], bh[g][o], bh[g][o + 1]);  // Ah*Bh
                    mma16816(acc[mi][ni], a[mi], bl[g][o], bl[g][o + 1]);  // Ah*Bl
                }
            #pragma unroll
            for (int mt = 0; mt < 4; mt++) ldsm4(a[mt], tAl + mt * (16 * 64) + koA);
            #pragma unroll
            for (int mi = 0; mi < 4; mi++)
                #pragma unroll
                for (int ni = 0; ni < 4; ni++) {
                    const int g = ni >> 1, o = (ni & 1) * 2;
                    mma16816(acc[mi][ni], a[mi], bh[g][o], bh[g][o + 1]);  // Al*Bh
                }
        }
    }

    const int gid = lane >> 2;
    const int tig = lane & 3;

    auto storePair = [&](int m, int n, float v0, float v1) {
        if (bias) { v0 += bias[n]; v1 += bias[n + 1]; }
        if (mode == 0) {
            float2 t; t.x = v0; t.y = v1;
            *reinterpret_cast<float2*>(&outF[(size_t)m * Ntot + n]) = t;
        } else {
            __nv_bfloat16 h0 = __float2bfloat16(v0);
            __nv_bfloat16 l0 = __float2bfloat16(v0 - __bfloat162float(h0));
            __nv_bfloat16 h1 = __float2bfloat16(v1);
            __nv_bfloat16 l1 = __float2bfloat16(v1 - __bfloat162float(h1));
            const int p  = n >> 11;                 // 0=q, 1=k, 2=v
            const int n2 = n & (HIDDEN - 1);
            const int b = m >> 11, s = m & (SSEQ - 1);
            const int h = n2 >> 7, d = n2 & (HDIM - 1);
            __nv_bfloat16* oh = (p == 0) ? o0h : ((p == 1) ? o1h : o2h);
            __nv_bfloat16* ol = (p == 0) ? o0l : ((p == 1) ? o1l : o2l);
            const size_t idx = (((size_t)(b * NHEAD + h) * SSEQ) + s) * HDIM + d;
            __nv_bfloat162 th; th.x = h0; th.y = h1;
            __nv_bfloat162 tl; tl.x = l0; tl.y = l1;
            *reinterpret_cast<__nv_bfloat162*>(&oh[idx]) = th;
            *reinterpret_cast<__nv_bfloat162*>(&ol[idx]) = tl;
        }
    };

    #pragma unroll
    for (int mi = 0; mi < 4; mi++) {
        #pragma unroll
        for (int ni = 0; ni < 4; ni++) {
            const int m = m0 + wm * 64 + mi * 16 + gid;
            const int n = n0 + wn * 32 + ni * 8 + tig * 2;
            storePair(m,     n, acc[mi][ni][0], acc[mi][ni][1]);
            storePair(m + 8, n, acc[mi][ni][2], acc[mi][ni][3]);
        }
    }
}

// ===================== fused flash attention (bf16x3, KV-split) =============
// R9 structure: 64 q-rows/CTA, 128 thr, 32-key stages, 3 stages, 2 CTAs/SM.
// blockIdx.z = KV split (keys [z*1024, (z+1)*1024)).  Epilogue stores fp32
// unnormalized partials + (m, l); fa_combine merges the splits.
#define FA_STRIDE  272                       // 128 bf16 + 8 pad
#define FA_KVTILE  (32 * FA_STRIDE)          // 8704
#define FA_STAGE   (4 * FA_KVTILE)           // Kh,Kl,Vh,Vl = 34816
#define FA_SMEM    (3 * FA_STAGE)            // 104448 -> 2 CTAs/SM
#define FA_QTILE   (64 * FA_STRIDE)          // 17408

__global__ void __launch_bounds__(128, 2)
fa_kernel(const __nv_bfloat16* __restrict__ qh, const __nv_bfloat16* __restrict__ ql,
          const __nv_bfloat16* __restrict__ kh, const __nv_bfloat16* __restrict__ kl,
          const __nv_bfloat16* __restrict__ vh, const __nv_bfloat16* __restrict__ vl,
          const float* __restrict__ mask,
          float* __restrict__ Op, float* __restrict__ Ml)
{
    extern __shared__ __align__(128) char smem[];
    const uint32_t sb   = smem_to_u32(smem);
    const uint32_t sStg = sb;

    const int tid  = threadIdx.x;
    const int lane = tid & 31;
    const int wid  = tid >> 5;           // 0..3
    const int gid  = lane >> 2;
    const int tig  = lane & 3;

    const int z   = blockIdx.y;
    const int q0  = blockIdx.x * 64;
    const int spl = blockIdx.z;
    const int b   = z >> 4;
    const int ko0 = spl * KV_PER_SPLIT;

    const size_t qBase  = ((size_t)z * SSEQ + q0) * HDIM;
    const size_t kvBase = (size_t)z * SSEQ * HDIM;

    // ---- Q tile (64 rows) staged into stage-2 area, then to registers
    const uint32_t sQh = sStg + 2 * FA_STAGE;
    const uint32_t sQl = sQh + FA_QTILE;
    #pragma unroll
    for (int ii = 0; ii < 8; ii++) {
        const int i = tid + ii * 128;
        const int r = i >> 4;
        const int c = i & 15;
        const uint32_t so = (uint32_t)(r * FA_STRIDE + c * 16);
        const size_t go = qBase + (size_t)r * HDIM + c * 8;
        CP_ASYNC16(sQh + so, (const char*)(qh + go));
        CP_ASYNC16(sQl + so, (const char*)(ql + go));
    }
    CP_ASYNC_COMMIT();                       // group: Q

    auto load_stage = [&](int st, int k0) {
        const uint32_t tb = sStg + st * FA_STAGE;
        #pragma unroll
        for (int ii = 0; ii < 4; ii++) {
            const int i = tid + ii * 128;
            const int r = i >> 4;
            const int c = i & 15;
            const uint32_t so = (uint32_t)(r * FA_STRIDE + c * 16);
            const size_t go = kvBase + (size_t)(k0 + r) * HDIM + c * 8;
            CP_ASYNC16(tb + 0 * FA_KVTILE + so, (const char*)(kh + go));
            CP_ASYNC16(tb + 1 * FA_KVTILE + so, (const char*)(kl + go));
            CP_ASYNC16(tb + 2 * FA_KVTILE + so, (const char*)(vh + go));
            CP_ASYNC16(tb + 3 * FA_KVTILE + so, (const char*)(vl + go));
        }
        CP_ASYNC_COMMIT();
    };
    load_stage(0, ko0);
    load_stage(1, ko0 + 32);

    // Q fragments -> registers
    const uint32_t aOff = (uint32_t)((16 * wid + (lane & 15)) * FA_STRIDE + (lane >> 4) * 16);
    uint32_t qA[8][4], qL[8][4];
    CP_ASYNC_WAIT(2);
    __syncthreads();
    #pragma unroll
    for (int kd = 0; kd < 8; kd++) {
        ldsm4(qA[kd], sQh + aOff + kd * 32);
        ldsm4(qL[kd], sQl + aOff + kd * 32);
    }

    float O[16][4];
    #pragma unroll
    for (int i = 0; i < 16; i++)
        #pragma unroll
        for (int j = 0; j < 4; j++) O[i][j] = 0.0f;
    float m0 = -1e30f, m1 = -1e30f, l0 = 0.0f, l1 = 0.0f;

    const uint32_t bOff = (uint32_t)(((lane & 7) + ((lane >> 4) & 1) * 8) * FA_STRIDE
                                     + ((lane >> 3) & 1) * 16);
    const uint32_t vOff = (uint32_t)(((lane & 7) + ((lane >> 3) & 1) * 8) * FA_STRIDE
                                     + ((lane >> 4) & 1) * 16);
    const float* mrow = mask + (size_t)b * SSEQ;
    const float LOG2E  = 1.4426950408889634f;
    const float scale2 = 0.08838834764831845f * LOG2E;   // (1/sqrt(128))*log2(e)

    for (int c = 0; c < FA_ITERS; c++) {
        if (c + 1 < FA_ITERS) { CP_ASYNC_WAIT(1); } else { CP_ASYNC_WAIT(0); }
        __syncthreads();
        if (c + 2 < FA_ITERS) load_stage((c + 2) % 3, ko0 + (c + 2) * 32);

        const uint32_t tb = sStg + (c % 3) * FA_STAGE;
        const int k0 = ko0 + c * 32;

        float S[4][4];
        #pragma unroll
        for (int i = 0; i < 4; i++)
            #pragma unroll
            for (int j = 0; j < 4; j++) S[i][j] = 0.0f;

        #pragma unroll
        for (int kd = 0; kd < 8; kd++) {
            #pragma unroll
            for (int np = 0; np < 2; np++) {
                uint32_t bH[4], bL[4];
                ldsm4(bH, tb + 0 * FA_KVTILE + bOff + np * (16 * FA_STRIDE) + kd * 32);
                ldsm4(bL, tb + 1 * FA_KVTILE + bOff + np * (16 * FA_STRIDE) + kd * 32);
                mma16816(S[2 * np],     qA[kd], bH[0], bH[1]);
                mma16816(S[2 * np],     qL[kd], bH[0], bH[1]);
                mma16816(S[2 * np],     qA[kd], bL[0], bL[1]);
                mma16816(S[2 * np + 1], qA[kd], bH[2], bH[3]);
                mma16816(S[2 * np + 1], qL[kd], bH[2], bH[3]);
                mma16816(S[2 * np + 1], qA[kd], bL[2], bL[3]);
            }
        }

        // ---- scale + mask (log2 domain)
        #pragma unroll
        for (int nt = 0; nt < 4; nt++) {
            const float2 mv = *reinterpret_cast<const float2*>(mrow + k0 + nt * 8 + 2 * tig);
            const float mx2 = mv.x * LOG2E;
            const float my2 = mv.y * LOG2E;
            S[nt][0] = fmaf(S[nt][0], scale2, mx2);
            S[nt][1] = fmaf(S[nt][1], scale2, my2);
            S[nt][2] = fmaf(S[nt][2], scale2, mx2);
            S[nt][3] = fmaf(S[nt][3], scale2, my2);
        }

        float mx0 = -1e30f, mx1 = -1e30f;
        #pragma unroll
        for (int nt = 0; nt < 4; nt++) {
            mx0 = fmaxf(mx0, fmaxf(S[nt][0], S[nt][1]));
            mx1 = fmaxf(mx1, fmaxf(S[nt][2], S[nt][3]));
        }
        mx0 = fmaxf(mx0, __shfl_xor_sync(0xFFFFFFFFu, mx0, 1));
        mx0 = fmaxf(mx0, __shfl_xor_sync(0xFFFFFFFFu, mx0, 2));
        mx1 = fmaxf(mx1, __shfl_xor_sync(0xFFFFFFFFu, mx1, 1));
        mx1 = fmaxf(mx1, __shfl_xor_sync(0xFFFFFFFFu, mx1, 2));

        const float nm0 = fmaxf(m0, mx0);
        const float nm1 = fmaxf(m1, mx1);
        const float ef0 = fast_exp2(m0 - nm0);
        const float ef1 = fast_exp2(m1 - nm1);

        float rs0 = 0.0f, rs1 = 0.0f;
        #pragma unroll
        for (int nt = 0; nt < 4; nt++) {
            S[nt][0] = fast_exp2(S[nt][0] - nm0);
            S[nt][1] = fast_exp2(S[nt][1] - nm0);
            S[nt][2] = fast_exp2(S[nt][2] - nm1);
            S[nt][3] = fast_exp2(S[nt][3] - nm1);
            rs0 += S[nt][0] + S[nt][1];
            rs1 += S[nt][2] + S[nt][3];
        }
        rs0 += __shfl_xor_sync(0xFFFFFFFFu, rs0, 1);
        rs0 += __shfl_xor_sync(0xFFFFFFFFu, rs0, 2);
        rs1 += __shfl_xor_sync(0xFFFFFFFFu, rs1, 1);
        rs1 += __shfl_xor_sync(0xFFFFFFFFu, rs1, 2);

        l0 = l0 * ef0 + rs0;
        l1 = l1 * ef1 + rs1;
        m0 = nm0; m1 = nm1;

        #pragma unroll
        for (int nt = 0; nt < 16; nt++) {
            O[nt][0] *= ef0; O[nt][1] *= ef0;
            O[nt][2] *= ef1; O[nt][3] *= ef1;
        }

        // ---- P (hi/lo) @ V
        #pragma unroll
        for (int ks = 0; ks < 2; ks++) {
            uint32_t paH[4], paL[4];
            #pragma unroll
            for (int q = 0; q < 2; q++) {
                const float* s4 = S[2 * ks + q];
                #pragma unroll
                for (int rr = 0; rr < 2; rr++) {
                    const float x = s4[rr * 2 + 0];
                    const float y = s4[rr * 2 + 1];
                    const __nv_bfloat16 hx = __float2bfloat16(x);
                    const __nv_bfloat16 hy = __float2bfloat16(y);
                    __nv_bfloat162 th; th.x = hx; th.y = hy;
                    __nv_bfloat162 tl;
                    tl.x = __float2bfloat16(x - __bfloat162float(hx));
                    tl.y = __float2bfloat16(y - __bfloat162float(hy));
                    paH[q * 2 + rr] = *reinterpret_cast<uint32_t*>(&th);
                    paL[q * 2 + rr] = *reinterpret_cast<uint32_t*>(&tl);
                }
            }
            #pragma unroll
            for (int ntp = 0; ntp < 8; ntp++) {
                uint32_t vH[4], vL[4];
                ldsm4t(vH, tb + 2 * FA_KVTILE + vOff + ks * (16 * FA_STRIDE) + ntp * 32);
                ldsm4t(vL, tb + 3 * FA_KVTILE + vOff + ks * (16 * FA_STRIDE) + ntp * 32);
                mma16816(O[2 * ntp],     paH, vH[0], vH[1]);
                mma16816(O[2 * ntp],     paL, vH[0], vH[1]);
                mma16816(O[2 * ntp],     paH, vL[0], vL[1]);
                mma16816(O[2 * ntp + 1], paH, vH[2], vH[3]);
                mma16816(O[2 * ntp + 1], paL, vH[2], vH[3]);
                mma16816(O[2 * ntp + 1], paH, vL[2], vL[3]);
            }
        }
    }

    // ---- epilogue: store UNNORMALIZED fp32 partials + (m, l)
    const int r0 = q0 + 16 * wid + gid;
    const int r1 = r0 + 8;
    float* OpS = Op + (((size_t)spl * BH + z) * SSEQ) * HDIM;
    #pragma unroll
    for (int nt = 0; nt < 16; nt++) {
        const int d = nt * 8 + 2 * tig;
        float2 t0; t0.x = O[nt][0]; t0.y = O[nt][1];
        float2 t1; t1.x = O[nt][2]; t1.y = O[nt][3];
        *reinterpret_cast<float2*>(&OpS[(size_t)r0 * HDIM + d]) = t0;
        *reinterpret_cast<float2*>(&OpS[(size_t)r1 * HDIM + d]) = t1;
    }
    if (tig == 0) {
        float* mlS = Ml + (((size_t)spl * BH + z) * SSEQ) * 2;
        mlS[(size_t)r0 * 2 + 0] = m0;
        mlS[(size_t)r0 * 2 + 1] = l0;
        mlS[(size_t)r1 * 2 + 0] = m1;
        mlS[(size_t)r1 * 2 + 1] = l1;
    }
}

// ---- combine the KV splits -> AO bf16 hi/lo [B,S,HIDDEN]
__global__ void __launch_bounds__(128)
fa_combine(const float* __restrict__ Op, const float* __restrict__ Ml,
           __nv_bfloat16* __restrict__ aoh, __nv_bfloat16* __restrict__ aol)
{
    const int row = blockIdx.x;          // z*SSEQ + s, 0..BH*SSEQ-1
    const int d   = threadIdx.x;         // 0..127
    const int z   = row >> 11;
    const int s   = row & (SSEQ - 1);
    const int b   = z >> 4;
    const int h   = z & (NHEAD - 1);

    const size_t rowsTot = (size_t)BH * SSEQ;
    const float m0 = Ml[(size_t)row * 2 + 0];
    const float l0 = Ml[(size_t)row * 2 + 1];
    const float m1 = Ml[(rowsTot + row) * 2 + 0];
    const float l1 = Ml[(rowsTot + row) * 2 + 1];

    const float M  = fmaxf(m0, m1);
    const float w0 = fast_exp2(m0 - M);
    const float w1 = fast_exp2(m1 - M);
    const float inv = 1.0f / (l0 * w0 + l1 * w1);

    const size_t i0 = (size_t)row * HDIM + d;
    const float v = (Op[i0] * w0 + Op[rowsTot * HDIM + i0] * w1) * inv;

    const __nv_bfloat16 hh = __float2bfloat16(v);
    const __nv_bfloat16 ll = __float2bfloat16(v - __bfloat162float(hh));
    const size_t oi = ((size_t)(b * SSEQ + s)) * HIDDEN + h * HDIM + d;
    aoh[oi] = hh;
    aol[oi] = ll;
}

// ===================== fp32 -> bf16 hi/lo split =============================
__global__ void __launch_bounds__(256)
split_bf16(const float* __restrict__ in, __nv_bfloat16* __restrict__ hi,
           __nv_bfloat16* __restrict__ lo, int n4)
{
    const int i = blockIdx.x * 256 + threadIdx.x;
    if (i >= n4) return;
    const float4 v = reinterpret_cast<const float4*>(in)[i];
    union { __nv_bfloat16 b[4]; uint2 u; } H, L;
    H.b[0] = __float2bfloat16(v.x);
    H.b[1] = __float2bfloat16(v.y);
    H.b[2] = __float2bfloat16(v.z);
    H.b[3] = __float2bfloat16(v.w);
    L.b[0] = __float2bfloat16(v.x - __bfloat162float(H.b[0]));
    L.b[1] = __float2bfloat16(v.y - __bfloat162float(H.b[1]));
    L.b[2] = __float2bfloat16(v.z - __bfloat162float(H.b[2]));
    L.b[3] = __float2bfloat16(v.w - __bfloat162float(H.b[3]));
    reinterpret_cast<uint2*>(hi)[i] = H.u;
    reinterpret_cast<uint2*>(lo)[i] = L.u;
}

// 4 weight matrices in one launch: blockIdx.y selects Wq/Wk/Wv/Wo.
__global__ void __launch_bounds__(256)
split_bf16_w4(const float* __restrict__ w0, const float* __restrict__ w1,
              const float* __restrict__ w2, const float* __restrict__ w3,
              __nv_bfloat16* __restrict__ w3h, __nv_bfloat16* __restrict__ w3l,
              __nv_bfloat16* __restrict__ woh, __nv_bfloat16* __restrict__ wol,
              int n4)
{
    const int i = blockIdx.x * 256 + threadIdx.x;
    if (i >= n4) return;
    const int p = blockIdx.y;
    const float* in = (p == 0) ? w0 : (p == 1) ? w1 : (p == 2) ? w2 : w3;
    const size_t wOff = (size_t)HIDDEN * HIDDEN / 4;   // in uint2 units
    __nv_bfloat16* hi;
    __nv_bfloat16* lo;
    size_t o;
    if (p < 3) { hi = w3h; lo = w3l; o = (size_t)p * wOff; }
    else       { hi = woh; lo = wol; o = 0; }

    const float4 v = reinterpret_cast<const float4*>(in)[i];
    union { __nv_bfloat16 b[4]; uint2 u; } H, L;
    H.b[0] = __float2bfloat16(v.x);
    H.b[1] = __float2bfloat16(v.y);
    H.b[2] = __float2bfloat16(v.z);
    H.b[3] = __float2bfloat16(v.w);
    L.b[0] = __float2bfloat16(v.x - __bfloat162float(H.b[0]));
    L.b[1] = __float2bfloat16(v.y - __bfloat162float(H.b[1]));
    L.b[2] = __float2bfloat16(v.z - __bfloat162float(H.b[2]));
    L.b[3] = __float2bfloat16(v.w - __bfloat162float(H.b[3]));
    reinterpret_cast<uint2*>(hi)[o + i] = H.u;
    reinterpret_cast<uint2*>(lo)[o + i] = L.u;
}

// bias concat: [bq | bk | bv]
__global__ void __launch_bounds__(256)
concat_bias(const float* __restrict__ a, const float* __restrict__ b,
            const float* __restrict__ c, float* __restrict__ o)
{
    const int i = blockIdx.x * 256 + threadIdx.x;
    if (i < HIDDEN)          o[i] = a[i];
    else if (i < 2 * HIDDEN) o[i] = b[i - HIDDEN];
    else if (i < 3 * HIDDEN) o[i] = c[i - 2 * HIDDEN];
}

// ---------------------------------------------------------------------------
extern "C" void kernel_launch(void* const* d_in, const int* in_sizes, int n_in,
                              void* d_out, int out_size)
{
    (void)in_sizes; (void)n_in; (void)out_size;
    const float* x    = (const float*)d_in[0];
    const float* mask = (const float*)d_in[1];
    const float* Wq   = (const float*)d_in[2];
    const float* bq   = (const float*)d_in[3];
    const float* Wk   = (const float*)d_in[4];
    const float* bk   = (const float*)d_in[5];
    const float* Wv   = (const float*)d_in[6];
    const float* bv   = (const float*)d_in[7];
    const float* Wo   = (const float*)d_in[8];
    const float* bo   = (const float*)d_in[9];
    float* out = (float*)d_out;

    __nv_bfloat16 *xh, *xl, *w3h, *w3l, *woh, *wol;
    __nv_bfloat16 *qh, *ql, *kh, *kl, *vh, *vl, *aoh, *aol;
    float *b3, *op, *ml;
    cudaGetSymbolAddress((void**)&xh,  g_xh);
    cudaGetSymbolAddress((void**)&xl,  g_xl);
    cudaGetSymbolAddress((void**)&w3h, g_w3h);
    cudaGetSymbolAddress((void**)&w3l, g_w3l);
    cudaGetSymbolAddress((void**)&woh, g_woh);
    cudaGetSymbolAddress((void**)&wol, g_wol);
    cudaGetSymbolAddress((void**)&b3,  g_b3);
    cudaGetSymbolAddress((void**)&qh,  g_qh);
    cudaGetSymbolAddress((void**)&ql,  g_ql);
    cudaGetSymbolAddress((void**)&kh,  g_kh);
    cudaGetSymbolAddress((void**)&kl,  g_kl);
    cudaGetSymbolAddress((void**)&vh,  g_vh);
    cudaGetSymbolAddress((void**)&vl,  g_vl);
    cudaGetSymbolAddress((void**)&aoh, g_aoh);
    cudaGetSymbolAddress((void**)&aol, g_aol);
    cudaGetSymbolAddress((void**)&op,  g_op);
    cudaGetSymbolAddress((void**)&ml,  g_ml);

    cudaFuncSetAttribute(tgemm_nt, cudaFuncAttributeMaxDynamicSharedMemorySize,
                         TG_SMEM);
    cudaFuncSetAttribute(fa_kernel, cudaFuncAttributeMaxDynamicSharedMemorySize,
                         FA_SMEM);

    // ---- hi/lo splits
    const int nX4 = (MROWS * HIDDEN) / 4;
    const int nW4 = (HIDDEN * HIDDEN) / 4;
    split_bf16<<<nX4 / 256, 256>>>(x, xh, xl, nX4);
    split_bf16_w4<<<dim3(nW4 / 256, 4), 256>>>(Wq, Wk, Wv, Wo,
                                               w3h, w3l, woh, wol, nW4);
    concat_bias<<<(3 * HIDDEN) / 256, 256>>>(bq, bk, bv, b3);

    // ---- fused QKV projection -> bf16 hi/lo [B,H,S,D] x3
    const dim3 gQKV(3 * HIDDEN / 128, MROWS / 128, 1);   // (48, 32)
    tgemm_nt<<<gQKV, 256, TG_SMEM>>>(xh, xl, w3h, w3l, b3, HIDDEN, 3 * HIDDEN, 1,
                                     nullptr, qh, ql, kh, kl, vh, vl);

    // ---- fused attention, KV-split -> fp32 partials
    const dim3 gFA(SSEQ / 64, BH, NSPLIT);   // (32, 32, 2) = 2048 CTAs
    fa_kernel<<<gFA, 128, FA_SMEM>>>(qh, ql, kh, kl, vh, vl, mask, op, ml);

    // ---- combine splits -> AO bf16 hi/lo
    fa_combine<<<BH * SSEQ, 128>>>(op, ml, aoh, aol);

    // ---- output projection (+bias) -> d_out
    const dim3 gO(HIDDEN / 128, MROWS / 128, 1);
    tgemm_nt<<<gO, 256, TG_SMEM>>>(aoh, aol, woh, wol, bo, HIDDEN, HIDDEN, 0,
                                   out, nullptr, nullptr, nullptr, nullptr,
                                   nullptr, nullptr);
}

// round 13
// speedup vs baseline: 1.0357x; 1.0357x over previous
#include <cuda_runtime.h>
#include <cuda_bf16.h>
#include <math.h>
#include <stdint.h>

// Problem constants
#define HIDDEN 2048
#define NHEAD  16
#define HDIM   128
#define BB     2
#define SSEQ   2048
#define BH     (BB * NHEAD)      // 32
#define MROWS  (BB * SSEQ)       // 4096

// ---------------- scratch (device globals; no allocation allowed) -----------
__device__ __align__(128) __nv_bfloat16 g_xh [(size_t)MROWS * HIDDEN];
__device__ __align__(128) __nv_bfloat16 g_xl [(size_t)MROWS * HIDDEN];
__device__ __align__(128) __nv_bfloat16 g_w3h[(size_t)3 * HIDDEN * HIDDEN];  // Wq|Wk|Wv
__device__ __align__(128) __nv_bfloat16 g_w3l[(size_t)3 * HIDDEN * HIDDEN];
__device__ __align__(128) __nv_bfloat16 g_woh[(size_t)HIDDEN * HIDDEN];
__device__ __align__(128) __nv_bfloat16 g_wol[(size_t)HIDDEN * HIDDEN];
__device__ __align__(128) float         g_b3 [3 * HIDDEN];                   // bq|bk|bv
__device__ __align__(128) __nv_bfloat16 g_qh [(size_t)BH * SSEQ * HDIM];  // [B,H,S,D]
__device__ __align__(128) __nv_bfloat16 g_ql [(size_t)BH * SSEQ * HDIM];
__device__ __align__(128) __nv_bfloat16 g_kh [(size_t)BH * SSEQ * HDIM];
__device__ __align__(128) __nv_bfloat16 g_kl [(size_t)BH * SSEQ * HDIM];
__device__ __align__(128) __nv_bfloat16 g_vh [(size_t)BH * SSEQ * HDIM];
__device__ __align__(128) __nv_bfloat16 g_vl [(size_t)BH * SSEQ * HDIM];
__device__ __align__(128) __nv_bfloat16 g_aoh[(size_t)MROWS * HIDDEN];
__device__ __align__(128) __nv_bfloat16 g_aol[(size_t)MROWS * HIDDEN];

// ============================ PTX helpers ====================================
__device__ __forceinline__ uint32_t smem_to_u32(const void* smem_ptr) {
    uint32_t addr;
    asm("{ .reg .u64 tmp; cvta.to.shared.u64 tmp, %1; cvt.u32.u64 %0, tmp; }"
        : "=r"(addr) : "l"(smem_ptr));
    return addr;
}
#define CP_ASYNC16(smem_u32, gptr) \
    asm volatile("cp.async.cg.shared.global [%0], [%1], 16;" \
        :: "r"((uint32_t)(smem_u32)), "l"(gptr) : "memory")
#define CP_ASYNC_COMMIT() asm volatile("cp.async.commit_group;" ::: "memory")
#define CP_ASYNC_WAIT(n)  asm volatile("cp.async.wait_group %0;" :: "n"(n) : "memory")

__device__ __forceinline__ void ldsm4(uint32_t* r, uint32_t addr) {
    asm volatile("ldmatrix.sync.aligned.m8n8.x4.shared.b16 {%0,%1,%2,%3}, [%4];"
        : "=r"(r[0]), "=r"(r[1]), "=r"(r[2]), "=r"(r[3]) : "r"(addr));
}
__device__ __forceinline__ void ldsm4t(uint32_t* r, uint32_t addr) {
    asm volatile("ldmatrix.sync.aligned.m8n8.x4.trans.shared.b16 {%0,%1,%2,%3}, [%4];"
        : "=r"(r[0]), "=r"(r[1]), "=r"(r[2]), "=r"(r[3]) : "r"(addr));
}
__device__ __forceinline__ void mma16816(float* d, const uint32_t* a,
                                         uint32_t b0, uint32_t b1) {
    asm volatile(
        "mma.sync.aligned.m16n8k16.row.col.f32.bf16.bf16.f32 "
        "{%0,%1,%2,%3}, {%4,%5,%6,%7}, {%8,%9}, {%0,%1,%2,%3};"
        : "+f"(d[0]), "+f"(d[1]), "+f"(d[2]), "+f"(d[3])
        : "r"(a[0]), "r"(a[1]), "r"(a[2]), "r"(a[3]), "r"(b0), "r"(b1));
}
__device__ __forceinline__ float fast_exp2(float x) {
    float y;
    asm("ex2.approx.f32 %0, %1;" : "=f"(y) : "f"(x));
    return y;
}

// ===================== HMMA bf16x3 NT GEMM ==================================
// C = (Ah+Al) @ (Bh+Bl)^T (+bias).  CTA tile 128x128, 4 warps of 64x64
// (halves ldsm duplication: A read 2x, B read 2x), K-chunk 32, XOR swizzle,
// 3-stage single-sync pipeline, 2 CTAs/SM.  Products: AhBh + AlBh + AhBl.
// mode 0: fp32 C[m*Ntot+n]; mode 1: fused-QKV bf16 hi/lo scatter [B,H,S,D].
#define TG_TILE     (128 * 64)              // 8192
#define TG_STAGE    (4 * TG_TILE)           // Ah, Al, Bh, Bl = 32768
#define TG_SMEM     (3 * TG_STAGE)          // 98304 -> 2 CTAs/SM

__global__ void __launch_bounds__(128, 2)
tgemm_nt(const __nv_bfloat16* __restrict__ Ah, const __nv_bfloat16* __restrict__ Al,
         const __nv_bfloat16* __restrict__ Bh, const __nv_bfloat16* __restrict__ Bl,
         const float* __restrict__ bias, int K, int Ntot, int mode,
         float* __restrict__ outF,
         __nv_bfloat16* __restrict__ o0h, __nv_bfloat16* __restrict__ o0l,
         __nv_bfloat16* __restrict__ o1h, __nv_bfloat16* __restrict__ o1l,
         __nv_bfloat16* __restrict__ o2h, __nv_bfloat16* __restrict__ o2l)
{
    extern __shared__ __align__(128) char smem[];
    const uint32_t sb = smem_to_u32(smem);

    const int tid  = threadIdx.x;
    const int lane = tid & 31;
    const int wid  = tid >> 5;          // 0..3
    const int wm   = wid >> 1;          // 0..1
    const int wn   = wid & 1;           // 0..1

    const int m0 = blockIdx.y * 128;
    const int n0 = blockIdx.x * 128;
    const int nch = K >> 5;             // K / 32

    const size_t aBase = (size_t)m0 * K;
    const size_t bBase = (size_t)n0 * K;

    float acc[4][8][4];
    #pragma unroll
    for (int i = 0; i < 4; i++)
        #pragma unroll
        for (int j = 0; j < 8; j++)
            #pragma unroll
            for (int t = 0; t < 4; t++) acc[i][j][t] = 0.0f;

    // stage loader: 4 tiles of [128 rows x 32 bf16], swizzled 64B rows
    auto load_chunk = [&](int buf, int k0) {
        const uint32_t tb = sb + buf * TG_STAGE;
        #pragma unroll
        for (int ii = 0; ii < 4; ii++) {
            const int i = tid + ii * 128;        // 0..511
            const int r = i >> 2;                // row 0..127
            const int c = i & 3;                 // 16B chunk 0..3
            const uint32_t so = (uint32_t)(r * 64 + ((c ^ ((r >> 1) & 3)) << 4));
            const size_t aOff = aBase + (size_t)r * K + k0 + c * 8;
            const size_t bOff = bBase + (size_t)r * K + k0 + c * 8;
            CP_ASYNC16(tb + 0 * TG_TILE + so, (const char*)(Ah + aOff));
            CP_ASYNC16(tb + 1 * TG_TILE + so, (const char*)(Al + aOff));
            CP_ASYNC16(tb + 2 * TG_TILE + so, (const char*)(Bh + bOff));
            CP_ASYNC16(tb + 3 * TG_TILE + so, (const char*)(Bl + bOff));
        }
        CP_ASYNC_COMMIT();
    };

    // per-lane swizzle constants
    const int hiA = lane >> 4;                       // 0/1 (k16 half)
    const int swA = ((lane & 15) >> 1) & 3;
    const uint32_t aRowOff = (uint32_t)((wm * 64 + (lane & 15)) * 64);
    const int hiB = (lane >> 3) & 1;
    const int swB = ((lane & 7) >> 1) & 3;
    const uint32_t bRowOff = (uint32_t)((wn * 64 + (lane & 7) + ((lane >> 4) & 1) * 8) * 64);

    load_chunk(0, 0);
    if (nch > 1) load_chunk(1, 32);

    for (int c = 0; c < nch; c++) {
        const int buf = c % 3;
        if (c + 1 < nch) { CP_ASYNC_WAIT(1); } else { CP_ASYNC_WAIT(0); }
        __syncthreads();
        if (c + 2 < nch) load_chunk((c + 2) % 3, (c + 2) * 32);

        const uint32_t tb  = sb + buf * TG_STAGE;
        const uint32_t tAh = tb + 0 * TG_TILE + aRowOff;
        const uint32_t tAl = tb + 1 * TG_TILE + aRowOff;
        const uint32_t tBh = tb + 2 * TG_TILE + bRowOff;
        const uint32_t tBl = tb + 3 * TG_TILE + bRowOff;

        #pragma unroll
        for (int ks = 0; ks < 2; ks++) {
            const uint32_t koA = (uint32_t)(((ks * 2 + hiA) ^ swA) << 4);
            const uint32_t koB = (uint32_t)(((ks * 2 + hiB) ^ swB) << 4);
            uint32_t a[4][4], bh[4][4], bl[4][4];
            // Ah + Bh + Bl
            #pragma unroll
            for (int mt = 0; mt < 4; mt++) ldsm4(a[mt], tAh + mt * (16 * 64) + koA);
            #pragma unroll
            for (int nt = 0; nt < 4; nt++) {
                ldsm4(bh[nt], tBh + nt * (16 * 64) + koB);
                ldsm4(bl[nt], tBl + nt * (16 * 64) + koB);
            }
            #pragma unroll
            for (int mi = 0; mi < 4; mi++)
                #pragma unroll
                for (int ni = 0; ni < 8; ni++) {
                    const int g = ni >> 1, o = (ni & 1) * 2;
                    mma16816(acc[mi][ni], a[mi], bh[g][o], bh[g][o + 1]);  // Ah*Bh
                    mma16816(acc[mi][ni], a[mi], bl[g][o], bl[g][o + 1]);  // Ah*Bl
                }
            // reload A regs with Al, then Al*Bh
            #pragma unroll
            for (int mt = 0; mt < 4; mt++) ldsm4(a[mt], tAl + mt * (16 * 64) + koA);
            #pragma unroll
            for (int mi = 0; mi < 4; mi++)
                #pragma unroll
                for (int ni = 0; ni < 8; ni++) {
                    const int g = ni >> 1, o = (ni & 1) * 2;
                    mma16816(acc[mi][ni], a[mi], bh[g][o], bh[g][o + 1]);  // Al*Bh
                }
        }
    }

    const int gid = lane >> 2;
    const int tig = lane & 3;

    auto storePair = [&](int m, int n, float v0, float v1) {
        if (bias) { v0 += bias[n]; v1 += bias[n + 1]; }
        if (mode == 0) {
            float2 t; t.x = v0; t.y = v1;
            *reinterpret_cast<float2*>(&outF[(size_t)m * Ntot + n]) = t;
        } else {
            __nv_bfloat16 h0 = __float2bfloat16(v0);
            __nv_bfloat16 l0 = __float2bfloat16(v0 - __bfloat162float(h0));
            __nv_bfloat16 h1 = __float2bfloat16(v1);
            __nv_bfloat16 l1 = __float2bfloat16(v1 - __bfloat162float(h1));
            const int p  = n >> 11;                 // 0=q, 1=k, 2=v
            const int n2 = n & (HIDDEN - 1);
            const int b = m >> 11, s = m & (SSEQ - 1);
            const int h = n2 >> 7, d = n2 & (HDIM - 1);
            __nv_bfloat16* oh = (p == 0) ? o0h : ((p == 1) ? o1h : o2h);
            __nv_bfloat16* ol = (p == 0) ? o0l : ((p == 1) ? o1l : o2l);
            const size_t idx = (((size_t)(b * NHEAD + h) * SSEQ) + s) * HDIM + d;
            __nv_bfloat162 th; th.x = h0; th.y = h1;
            __nv_bfloat162 tl; tl.x = l0; tl.y = l1;
            *reinterpret_cast<__nv_bfloat162*>(&oh[idx]) = th;
            *reinterpret_cast<__nv_bfloat162*>(&ol[idx]) = tl;
        }
    };

    #pragma unroll
    for (int mi = 0; mi < 4; mi++) {
        #pragma unroll
        for (int ni = 0; ni < 8; ni++) {
            const int m = m0 + wm * 64 + mi * 16 + gid;
            const int n = n0 + wn * 64 + ni * 8 + tig * 2;
            storePair(m,     n, acc[mi][ni][0], acc[mi][ni][1]);
            storePair(m + 8, n, acc[mi][ni][2], acc[mi][ni][3]);
        }
    }
}

// ===================== fused flash attention (bf16x3) =======================
// R9 form (best known): 64 q-rows/CTA, 128 thr, 32-key stages, 3 stages,
// 2 CTAs/SM, Q in registers, log2-domain softmax.
#define FA_STRIDE  272                       // 128 bf16 + 8 pad
#define FA_KVTILE  (32 * FA_STRIDE)          // 8704
#define FA_STAGE   (4 * FA_KVTILE)           // Kh,Kl,Vh,Vl = 34816
#define FA_SMEM    (3 * FA_STAGE)            // 104448 -> 2 CTAs/SM
#define FA_QTILE   (64 * FA_STRIDE)          // 17408

__global__ void __launch_bounds__(128, 2)
fa_kernel(const __nv_bfloat16* __restrict__ qh, const __nv_bfloat16* __restrict__ ql,
          const __nv_bfloat16* __restrict__ kh, const __nv_bfloat16* __restrict__ kl,
          const __nv_bfloat16* __restrict__ vh, const __nv_bfloat16* __restrict__ vl,
          const float* __restrict__ mask,
          __nv_bfloat16* __restrict__ aoh, __nv_bfloat16* __restrict__ aol)
{
    extern __shared__ __align__(128) char smem[];
    const uint32_t sb   = smem_to_u32(smem);
    const uint32_t sStg = sb;

    const int tid  = threadIdx.x;
    const int lane = tid & 31;
    const int wid  = tid >> 5;           // 0..3
    const int gid  = lane >> 2;
    const int tig  = lane & 3;

    const int z  = blockIdx.y;
    const int q0 = blockIdx.x * 64;
    const int b  = z >> 4;
    const int h  = z & (NHEAD - 1);

    const size_t qBase  = ((size_t)z * SSEQ + q0) * HDIM;
    const size_t kvBase = (size_t)z * SSEQ * HDIM;

    // ---- Q tile (64 rows) into stage buf 2 (temporarily), then to registers
    const uint32_t sQh = sStg + 2 * FA_STAGE;
    const uint32_t sQl = sQh + FA_QTILE;
    #pragma unroll
    for (int ii = 0; ii < 8; ii++) {
        const int i = tid + ii * 128;            // 0..1023
        const int r = i >> 4;                    // 0..63
        const int c = i & 15;
        const uint32_t so = (uint32_t)(r * FA_STRIDE + c * 16);
        const size_t go = qBase + (size_t)r * HDIM + c * 8;
        CP_ASYNC16(sQh + so, (const char*)(qh + go));
        CP_ASYNC16(sQl + so, (const char*)(ql + go));
    }
    CP_ASYNC_COMMIT();                       // group: Q

    auto load_stage = [&](int st, int k0) {
        const uint32_t tb = sStg + st * FA_STAGE;
        #pragma unroll
        for (int ii = 0; ii < 4; ii++) {
            const int i = tid + ii * 128;        // 0..511
            const int r = i >> 4;                // 0..31
            const int c = i & 15;
            const uint32_t so = (uint32_t)(r * FA_STRIDE + c * 16);
            const size_t go = kvBase + (size_t)(k0 + r) * HDIM + c * 8;
            CP_ASYNC16(tb + 0 * FA_KVTILE + so, (const char*)(kh + go));
            CP_ASYNC16(tb + 1 * FA_KVTILE + so, (const char*)(kl + go));
            CP_ASYNC16(tb + 2 * FA_KVTILE + so, (const char*)(vh + go));
            CP_ASYNC16(tb + 3 * FA_KVTILE + so, (const char*)(vl + go));
        }
        CP_ASYNC_COMMIT();
    };
    load_stage(0, 0);
    load_stage(1, 32);

    // Q fragments -> registers (wait for Q group: 2 outstanding KV groups left)
    const uint32_t aOff = (uint32_t)((16 * wid + (lane & 15)) * FA_STRIDE + (lane >> 4) * 16);
    uint32_t qA[8][4], qL[8][4];
    CP_ASYNC_WAIT(2);
    __syncthreads();
    #pragma unroll
    for (int kd = 0; kd < 8; kd++) {
        ldsm4(qA[kd], sQh + aOff + kd * 32);
        ldsm4(qL[kd], sQl + aOff + kd * 32);
    }

    float O[16][4];
    #pragma unroll
    for (int i = 0; i < 16; i++)
        #pragma unroll
        for (int j = 0; j < 4; j++) O[i][j] = 0.0f;
    float m0 = -1e30f, m1 = -1e30f, l0 = 0.0f, l1 = 0.0f;

    const uint32_t bOff = (uint32_t)(((lane & 7) + ((lane >> 4) & 1) * 8) * FA_STRIDE
                                     + ((lane >> 3) & 1) * 16);
    const uint32_t vOff = (uint32_t)(((lane & 7) + ((lane >> 3) & 1) * 8) * FA_STRIDE
                                     + ((lane >> 4) & 1) * 16);
    const float* mrow = mask + (size_t)b * SSEQ;
    const float LOG2E  = 1.4426950408889634f;
    const float scale2 = 0.08838834764831845f * LOG2E;   // (1/sqrt(128))*log2(e)

    for (int c = 0; c < 64; c++) {
        if (c + 1 < 64) { CP_ASYNC_WAIT(1); } else { CP_ASYNC_WAIT(0); }
        __syncthreads();
        if (c + 2 < 64) load_stage((c + 2) % 3, (c + 2) * 32);

        const uint32_t tb = sStg + (c % 3) * FA_STAGE;
        const int k0 = c * 32;

        float S[4][4];
        #pragma unroll
        for (int i = 0; i < 4; i++)
            #pragma unroll
            for (int j = 0; j < 4; j++) S[i][j] = 0.0f;

        #pragma unroll
        for (int kd = 0; kd < 8; kd++) {
            #pragma unroll
            for (int np = 0; np < 2; np++) {
                uint32_t bH[4], bL[4];
                ldsm4(bH, tb + 0 * FA_KVTILE + bOff + np * (16 * FA_STRIDE) + kd * 32);
                ldsm4(bL, tb + 1 * FA_KVTILE + bOff + np * (16 * FA_STRIDE) + kd * 32);
                mma16816(S[2 * np],     qA[kd], bH[0], bH[1]);
                mma16816(S[2 * np],     qL[kd], bH[0], bH[1]);
                mma16816(S[2 * np],     qA[kd], bL[0], bL[1]);
                mma16816(S[2 * np + 1], qA[kd], bH[2], bH[3]);
                mma16816(S[2 * np + 1], qL[kd], bH[2], bH[3]);
                mma16816(S[2 * np + 1], qA[kd], bL[2], bL[3]);
            }
        }

        // ---- scale + mask (log2 domain)
        #pragma unroll
        for (int nt = 0; nt < 4; nt++) {
            const float2 mv = *reinterpret_cast<const float2*>(mrow + k0 + nt * 8 + 2 * tig);
            const float mx2 = mv.x * LOG2E;
            const float my2 = mv.y * LOG2E;
            S[nt][0] = fmaf(S[nt][0], scale2, mx2);
            S[nt][1] = fmaf(S[nt][1], scale2, my2);
            S[nt][2] = fmaf(S[nt][2], scale2, mx2);
            S[nt][3] = fmaf(S[nt][3], scale2, my2);
        }

        float mx0 = -1e30f, mx1 = -1e30f;
        #pragma unroll
        for (int nt = 0; nt < 4; nt++) {
            mx0 = fmaxf(mx0, fmaxf(S[nt][0], S[nt][1]));
            mx1 = fmaxf(mx1, fmaxf(S[nt][2], S[nt][3]));
        }
        mx0 = fmaxf(mx0, __shfl_xor_sync(0xFFFFFFFFu, mx0, 1));
        mx0 = fmaxf(mx0, __shfl_xor_sync(0xFFFFFFFFu, mx0, 2));
        mx1 = fmaxf(mx1, __shfl_xor_sync(0xFFFFFFFFu, mx1, 1));
        mx1 = fmaxf(mx1, __shfl_xor_sync(0xFFFFFFFFu, mx1, 2));

        const float nm0 = fmaxf(m0, mx0);
        const float nm1 = fmaxf(m1, mx1);
        const float ef0 = fast_exp2(m0 - nm0);
        const float ef1 = fast_exp2(m1 - nm1);

        float rs0 = 0.0f, rs1 = 0.0f;
        #pragma unroll
        for (int nt = 0; nt < 4; nt++) {
            S[nt][0] = fast_exp2(S[nt][0] - nm0);
            S[nt][1] = fast_exp2(S[nt][1] - nm0);
            S[nt][2] = fast_exp2(S[nt][2] - nm1);
            S[nt][3] = fast_exp2(S[nt][3] - nm1);
            rs0 += S[nt][0] + S[nt][1];
            rs1 += S[nt][2] + S[nt][3];
        }
        rs0 += __shfl_xor_sync(0xFFFFFFFFu, rs0, 1);
        rs0 += __shfl_xor_sync(0xFFFFFFFFu, rs0, 2);
        rs1 += __shfl_xor_sync(0xFFFFFFFFu, rs1, 1);
        rs1 += __shfl_xor_sync(0xFFFFFFFFu, rs1, 2);

        l0 = l0 * ef0 + rs0;
        l1 = l1 * ef1 + rs1;
        m0 = nm0; m1 = nm1;

        #pragma unroll
        for (int nt = 0; nt < 16; nt++) {
            O[nt][0] *= ef0; O[nt][1] *= ef0;
            O[nt][2] *= ef1; O[nt][3] *= ef1;
        }

        // ---- P (hi/lo) @ V
        #pragma unroll
        for (int ks = 0; ks < 2; ks++) {
            uint32_t paH[4], paL[4];
            #pragma unroll
            for (int q = 0; q < 2; q++) {
                const float* s4 = S[2 * ks + q];
                #pragma unroll
                for (int rr = 0; rr < 2; rr++) {
                    const float x = s4[rr * 2 + 0];
                    const float y = s4[rr * 2 + 1];
                    const __nv_bfloat16 hx = __float2bfloat16(x);
                    const __nv_bfloat16 hy = __float2bfloat16(y);
                    __nv_bfloat162 th; th.x = hx; th.y = hy;
                    __nv_bfloat162 tl;
                    tl.x = __float2bfloat16(x - __bfloat162float(hx));
                    tl.y = __float2bfloat16(y - __bfloat162float(hy));
                    paH[q * 2 + rr] = *reinterpret_cast<uint32_t*>(&th);
                    paL[q * 2 + rr] = *reinterpret_cast<uint32_t*>(&tl);
                }
            }
            #pragma unroll
            for (int ntp = 0; ntp < 8; ntp++) {
                uint32_t vH[4], vL[4];
                ldsm4t(vH, tb + 2 * FA_KVTILE + vOff + ks * (16 * FA_STRIDE) + ntp * 32);
                ldsm4t(vL, tb + 3 * FA_KVTILE + vOff + ks * (16 * FA_STRIDE) + ntp * 32);
                mma16816(O[2 * ntp],     paH, vH[0], vH[1]);
                mma16816(O[2 * ntp],     paL, vH[0], vH[1]);
                mma16816(O[2 * ntp],     paH, vL[0], vL[1]);
                mma16816(O[2 * ntp + 1], paH, vH[2], vH[3]);
                mma16816(O[2 * ntp + 1], paL, vH[2], vH[3]);
                mma16816(O[2 * ntp + 1], paH, vL[2], vL[3]);
            }
        }
    }

    const float inv0 = 1.0f / l0;
    const float inv1 = 1.0f / l1;
    const int r0 = q0 + 16 * wid + gid;
    const int r1 = r0 + 8;
    #pragma unroll
    for (int nt = 0; nt < 16; nt++) {
        const int d = h * HDIM + nt * 8 + 2 * tig;
        const size_t i0 = ((size_t)b * SSEQ + r0) * HIDDEN + d;
        const size_t i1 = ((size_t)b * SSEQ + r1) * HIDDEN + d;
        const float v00 = O[nt][0] * inv0, v01 = O[nt][1] * inv0;
        const float v10 = O[nt][2] * inv1, v11 = O[nt][3] * inv1;

        const __nv_bfloat16 h00 = __float2bfloat16(v00);
        const __nv_bfloat16 h01 = __float2bfloat16(v01);
        const __nv_bfloat16 h10 = __float2bfloat16(v10);
        const __nv_bfloat16 h11 = __float2bfloat16(v11);
        __nv_bfloat162 th0; th0.x = h00; th0.y = h01;
        __nv_bfloat162 th1; th1.x = h10; th1.y = h11;
        __nv_bfloat162 tl0;
        tl0.x = __float2bfloat16(v00 - __bfloat162float(h00));
        tl0.y = __float2bfloat16(v01 - __bfloat162float(h01));
        __nv_bfloat162 tl1;
        tl1.x = __float2bfloat16(v10 - __bfloat162float(h10));
        tl1.y = __float2bfloat16(v11 - __bfloat162float(h11));
        *reinterpret_cast<__nv_bfloat162*>(&aoh[i0]) = th0;
        *reinterpret_cast<__nv_bfloat162*>(&aol[i0]) = tl0;
        *reinterpret_cast<__nv_bfloat162*>(&aoh[i1]) = th1;
        *reinterpret_cast<__nv_bfloat162*>(&aol[i1]) = tl1;
    }
}

// ===================== fp32 -> bf16 hi/lo split =============================
__global__ void __launch_bounds__(256)
split_bf16(const float* __restrict__ in, __nv_bfloat16* __restrict__ hi,
           __nv_bfloat16* __restrict__ lo, int n4)
{
    const int i = blockIdx.x * 256 + threadIdx.x;
    if (i >= n4) return;
    const float4 v = reinterpret_cast<const float4*>(in)[i];
    union { __nv_bfloat16 b[4]; uint2 u; } H, L;
    H.b[0] = __float2bfloat16(v.x);
    H.b[1] = __float2bfloat16(v.y);
    H.b[2] = __float2bfloat16(v.z);
    H.b[3] = __float2bfloat16(v.w);
    L.b[0] = __float2bfloat16(v.x - __bfloat162float(H.b[0]));
    L.b[1] = __float2bfloat16(v.y - __bfloat162float(H.b[1]));
    L.b[2] = __float2bfloat16(v.z - __bfloat162float(H.b[2]));
    L.b[3] = __float2bfloat16(v.w - __bfloat162float(H.b[3]));
    reinterpret_cast<uint2*>(hi)[i] = H.u;
    reinterpret_cast<uint2*>(lo)[i] = L.u;
}

// 4 weight matrices in one launch: blockIdx.y selects Wq/Wk/Wv/Wo.
__global__ void __launch_bounds__(256)
split_bf16_w4(const float* __restrict__ w0, const float* __restrict__ w1,
              const float* __restrict__ w2, const float* __restrict__ w3,
              __nv_bfloat16* __restrict__ w3h, __nv_bfloat16* __restrict__ w3l,
              __nv_bfloat16* __restrict__ woh, __nv_bfloat16* __restrict__ wol,
              int n4)
{
    const int i = blockIdx.x * 256 + threadIdx.x;
    if (i >= n4) return;
    const int p = blockIdx.y;
    const float* in = (p == 0) ? w0 : (p == 1) ? w1 : (p == 2) ? w2 : w3;
    const size_t wOff = (size_t)HIDDEN * HIDDEN / 4;   // in uint2 units
    __nv_bfloat16* hi;
    __nv_bfloat16* lo;
    size_t o;
    if (p < 3) { hi = w3h; lo = w3l; o = (size_t)p * wOff; }
    else       { hi = woh; lo = wol; o = 0; }

    const float4 v = reinterpret_cast<const float4*>(in)[i];
    union { __nv_bfloat16 b[4]; uint2 u; } H, L;
    H.b[0] = __float2bfloat16(v.x);
    H.b[1] = __float2bfloat16(v.y);
    H.b[2] = __float2bfloat16(v.z);
    H.b[3] = __float2bfloat16(v.w);
    L.b[0] = __float2bfloat16(v.x - __bfloat162float(H.b[0]));
    L.b[1] = __float2bfloat16(v.y - __bfloat162float(H.b[1]));
    L.b[2] = __float2bfloat16(v.z - __bfloat162float(H.b[2]));
    L.b[3] = __float2bfloat16(v.w - __bfloat162float(H.b[3]));
    reinterpret_cast<uint2*>(hi)[o + i] = H.u;
    reinterpret_cast<uint2*>(lo)[o + i] = L.u;
}

// bias concat: [bq | bk | bv]
__global__ void __launch_bounds__(256)
concat_bias(const float* __restrict__ a, const float* __restrict__ b,
            const float* __restrict__ c, float* __restrict__ o)
{
    const int i = blockIdx.x * 256 + threadIdx.x;
    if (i < HIDDEN)          o[i] = a[i];
    else if (i < 2 * HIDDEN) o[i] = b[i - HIDDEN];
    else if (i < 3 * HIDDEN) o[i] = c[i - 2 * HIDDEN];
}

// ---------------------------------------------------------------------------
extern "C" void kernel_launch(void* const* d_in, const int* in_sizes, int n_in,
                              void* d_out, int out_size)
{
    (void)in_sizes; (void)n_in; (void)out_size;
    const float* x    = (const float*)d_in[0];
    const float* mask = (const float*)d_in[1];
    const float* Wq   = (const float*)d_in[2];
    const float* bq   = (const float*)d_in[3];
    const float* Wk   = (const float*)d_in[4];
    const float* bk   = (const float*)d_in[5];
    const float* Wv   = (const float*)d_in[6];
    const float* bv   = (const float*)d_in[7];
    const float* Wo   = (const float*)d_in[8];
    const float* bo   = (const float*)d_in[9];
    float* out = (float*)d_out;

    __nv_bfloat16 *xh, *xl, *w3h, *w3l, *woh, *wol;
    __nv_bfloat16 *qh, *ql, *kh, *kl, *vh, *vl, *aoh, *aol;
    float* b3;
    cudaGetSymbolAddress((void**)&xh,  g_xh);
    cudaGetSymbolAddress((void**)&xl,  g_xl);
    cudaGetSymbolAddress((void**)&w3h, g_w3h);
    cudaGetSymbolAddress((void**)&w3l, g_w3l);
    cudaGetSymbolAddress((void**)&woh, g_woh);
    cudaGetSymbolAddress((void**)&wol, g_wol);
    cudaGetSymbolAddress((void**)&b3,  g_b3);
    cudaGetSymbolAddress((void**)&qh,  g_qh);
    cudaGetSymbolAddress((void**)&ql,  g_ql);
    cudaGetSymbolAddress((void**)&kh,  g_kh);
    cudaGetSymbolAddress((void**)&kl,  g_kl);
    cudaGetSymbolAddress((void**)&vh,  g_vh);
    cudaGetSymbolAddress((void**)&vl,  g_vl);
    cudaGetSymbolAddress((void**)&aoh, g_aoh);
    cudaGetSymbolAddress((void**)&aol, g_aol);

    cudaFuncSetAttribute(tgemm_nt, cudaFuncAttributeMaxDynamicSharedMemorySize,
                         TG_SMEM);
    cudaFuncSetAttribute(fa_kernel, cudaFuncAttributeMaxDynamicSharedMemorySize,
                         FA_SMEM);

    // ---- hi/lo splits
    const int nX4 = (MROWS * HIDDEN) / 4;
    const int nW4 = (HIDDEN * HIDDEN) / 4;
    split_bf16<<<nX4 / 256, 256>>>(x, xh, xl, nX4);
    split_bf16_w4<<<dim3(nW4 / 256, 4), 256>>>(Wq, Wk, Wv, Wo,
                                               w3h, w3l, woh, wol, nW4);
    concat_bias<<<(3 * HIDDEN) / 256, 256>>>(bq, bk, bv, b3);

    // ---- fused QKV projection -> bf16 hi/lo [B,H,S,D] x3
    const dim3 gQKV(3 * HIDDEN / 128, MROWS / 128, 1);   // (48, 32)
    tgemm_nt<<<gQKV, 128, TG_SMEM>>>(xh, xl, w3h, w3l, b3, HIDDEN, 3 * HIDDEN, 1,
                                     nullptr, qh, ql, kh, kl, vh, vl);

    // ---- fused attention -> AO bf16 hi/lo [B,S,HIDDEN]
    const dim3 gFA(SSEQ / 64, BH, 1);   // (32, 32) = 1024 CTAs
    fa_kernel<<<gFA, 128, FA_SMEM>>>(qh, ql, kh, kl, vh, vl, mask, aoh, aol);

    // ---- output projection (+bias) -> d_out
    const dim3 gO(HIDDEN / 128, MROWS / 128, 1);
    tgemm_nt<<<gO, 128, TG_SMEM>>>(aoh, aol, woh, wol, bo, HIDDEN, HIDDEN, 0,
                                   out, nullptr, nullptr, nullptr, nullptr,
                                   nullptr, nullptr);
}

// round 14
// speedup vs baseline: 1.3600x; 1.3131x over previous
#include <cuda_runtime.h>
#include <cuda_fp16.h>
#include <math.h>
#include <stdint.h>

// Problem constants
#define HIDDEN 2048
#define NHEAD  16
#define HDIM   128
#define BB     2
#define SSEQ   2048
#define BH     (BB * NHEAD)      // 32
#define MROWS  (BB * SSEQ)       // 4096

// ---------------- scratch (device globals; no allocation allowed) -----------
__device__ __align__(128) __half g_x  [(size_t)MROWS * HIDDEN];              // fp16 single
__device__ __align__(128) __half g_w3h[(size_t)3 * HIDDEN * HIDDEN];         // Wq|Wk|Wv hi
__device__ __align__(128) __half g_w3l[(size_t)3 * HIDDEN * HIDDEN];         // lo
__device__ __align__(128) __half g_woh[(size_t)HIDDEN * HIDDEN];
__device__ __align__(128) __half g_wol[(size_t)HIDDEN * HIDDEN];
__device__ __align__(128) float  g_b3 [3 * HIDDEN];                          // bq|bk|bv
__device__ __align__(128) __half g_q  [(size_t)BH * SSEQ * HDIM];  // [B,H,S,D] single
__device__ __align__(128) __half g_kh [(size_t)BH * SSEQ * HDIM];
__device__ __align__(128) __half g_kl [(size_t)BH * SSEQ * HDIM];
__device__ __align__(128) __half g_vh [(size_t)BH * SSEQ * HDIM];
__device__ __align__(128) __half g_vl [(size_t)BH * SSEQ * HDIM];
__device__ __align__(128) __half g_ao [(size_t)MROWS * HIDDEN];              // single

// ============================ PTX helpers ====================================
__device__ __forceinline__ uint32_t smem_to_u32(const void* smem_ptr) {
    uint32_t addr;
    asm("{ .reg .u64 tmp; cvta.to.shared.u64 tmp, %1; cvt.u32.u64 %0, tmp; }"
        : "=r"(addr) : "l"(smem_ptr));
    return addr;
}
#define CP_ASYNC16(smem_u32, gptr) \
    asm volatile("cp.async.cg.shared.global [%0], [%1], 16;" \
        :: "r"((uint32_t)(smem_u32)), "l"(gptr) : "memory")
#define CP_ASYNC_COMMIT() asm volatile("cp.async.commit_group;" ::: "memory")
#define CP_ASYNC_WAIT(n)  asm volatile("cp.async.wait_group %0;" :: "n"(n) : "memory")

__device__ __forceinline__ void ldsm4(uint32_t* r, uint32_t addr) {
    asm volatile("ldmatrix.sync.aligned.m8n8.x4.shared.b16 {%0,%1,%2,%3}, [%4];"
        : "=r"(r[0]), "=r"(r[1]), "=r"(r[2]), "=r"(r[3]) : "r"(addr));
}
__device__ __forceinline__ void ldsm4t(uint32_t* r, uint32_t addr) {
    asm volatile("ldmatrix.sync.aligned.m8n8.x4.trans.shared.b16 {%0,%1,%2,%3}, [%4];"
        : "=r"(r[0]), "=r"(r[1]), "=r"(r[2]), "=r"(r[3]) : "r"(addr));
}
// fp16 inputs, fp32 accumulate
__device__ __forceinline__ void mma16816(float* d, const uint32_t* a,
                                         uint32_t b0, uint32_t b1) {
    asm volatile(
        "mma.sync.aligned.m16n8k16.row.col.f32.f16.f16.f32 "
        "{%0,%1,%2,%3}, {%4,%5,%6,%7}, {%8,%9}, {%0,%1,%2,%3};"
        : "+f"(d[0]), "+f"(d[1]), "+f"(d[2]), "+f"(d[3])
        : "r"(a[0]), "r"(a[1]), "r"(a[2]), "r"(a[3]), "r"(b0), "r"(b1));
}
__device__ __forceinline__ float fast_exp2(float x) {
    float y;
    asm("ex2.approx.f32 %0, %1;" : "=f"(y) : "f"(x));
    return y;
}
__device__ __forceinline__ uint32_t pack_half2(float a, float b) {
    __half2 t; t.x = __float2half_rn(a); t.y = __float2half_rn(b);
    return *reinterpret_cast<uint32_t*>(&t);
}

// ===================== HMMA fp16x2 NT GEMM ==================================
// C = A @ (Bh+Bl)^T (+bias).  A: [M,K] fp16 row-major (single precision term),
// B*: [Ntot,K] fp16 hi/lo.  Products: A*Bh + A*Bl  (error ~2^-12 rel).
// CTA tile 128x128, 4 warps of 64x64, K-chunk 32, XOR swizzle, 3-stage
// single-sync pipeline, 2 CTAs/SM.
// mode 0: fp32 C[m*Ntot+n]
// mode 1: fused-QKV scatter [B,H,S,D]: q -> single fp16; k, v -> fp16 hi/lo.
#define TG_TILE     (128 * 64)              // 8192
#define TG_STAGE    (3 * TG_TILE)           // A, Bh, Bl = 24576
#define TG_SMEM     (3 * TG_STAGE)          // 73728 -> 2 CTAs/SM

__global__ void __launch_bounds__(128, 2)
tgemm_nt(const __half* __restrict__ A,
         const __half* __restrict__ Bh, const __half* __restrict__ Bl,
         const float* __restrict__ bias, int K, int Ntot, int mode,
         float* __restrict__ outF,
         __half* __restrict__ oq,
         __half* __restrict__ okh, __half* __restrict__ okl,
         __half* __restrict__ ovh, __half* __restrict__ ovl)
{
    extern __shared__ __align__(128) char smem[];
    const uint32_t sb = smem_to_u32(smem);

    const int tid  = threadIdx.x;
    const int lane = tid & 31;
    const int wid  = tid >> 5;          // 0..3
    const int wm   = wid >> 1;          // 0..1
    const int wn   = wid & 1;           // 0..1

    const int m0 = blockIdx.y * 128;
    const int n0 = blockIdx.x * 128;
    const int nch = K >> 5;             // K / 32

    const size_t aBase = (size_t)m0 * K;
    const size_t bBase = (size_t)n0 * K;

    float acc[4][8][4];
    #pragma unroll
    for (int i = 0; i < 4; i++)
        #pragma unroll
        for (int j = 0; j < 8; j++)
            #pragma unroll
            for (int t = 0; t < 4; t++) acc[i][j][t] = 0.0f;

    // stage loader: 3 tiles of [128 rows x 32 fp16], swizzled 64B rows
    auto load_chunk = [&](int buf, int k0) {
        const uint32_t tb = sb + buf * TG_STAGE;
        #pragma unroll
        for (int ii = 0; ii < 4; ii++) {
            const int i = tid + ii * 128;        // 0..511
            const int r = i >> 2;                // row 0..127
            const int c = i & 3;                 // 16B chunk 0..3
            const uint32_t so = (uint32_t)(r * 64 + ((c ^ ((r >> 1) & 3)) << 4));
            const size_t aOff = aBase + (size_t)r * K + k0 + c * 8;
            const size_t bOff = bBase + (size_t)r * K + k0 + c * 8;
            CP_ASYNC16(tb + 0 * TG_TILE + so, (const char*)(A  + aOff));
            CP_ASYNC16(tb + 1 * TG_TILE + so, (const char*)(Bh + bOff));
            CP_ASYNC16(tb + 2 * TG_TILE + so, (const char*)(Bl + bOff));
        }
        CP_ASYNC_COMMIT();
    };

    // per-lane swizzle constants
    const int hiA = lane >> 4;                       // 0/1 (k16 half)
    const int swA = ((lane & 15) >> 1) & 3;
    const uint32_t aRowOff = (uint32_t)((wm * 64 + (lane & 15)) * 64);
    const int hiB = (lane >> 3) & 1;
    const int swB = ((lane & 7) >> 1) & 3;
    const uint32_t bRowOff = (uint32_t)((wn * 64 + (lane & 7) + ((lane >> 4) & 1) * 8) * 64);

    load_chunk(0, 0);
    if (nch > 1) load_chunk(1, 32);

    for (int c = 0; c < nch; c++) {
        const int buf = c % 3;
        if (c + 1 < nch) { CP_ASYNC_WAIT(1); } else { CP_ASYNC_WAIT(0); }
        __syncthreads();
        if (c + 2 < nch) load_chunk((c + 2) % 3, (c + 2) * 32);

        const uint32_t tb  = sb + buf * TG_STAGE;
        const uint32_t tA  = tb + 0 * TG_TILE + aRowOff;
        const uint32_t tBh = tb + 1 * TG_TILE + bRowOff;
        const uint32_t tBl = tb + 2 * TG_TILE + bRowOff;

        #pragma unroll
        for (int ks = 0; ks < 2; ks++) {
            const uint32_t koA = (uint32_t)(((ks * 2 + hiA) ^ swA) << 4);
            const uint32_t koB = (uint32_t)(((ks * 2 + hiB) ^ swB) << 4);
            uint32_t a[4][4], bh[4][4], bl[4][4];
            #pragma unroll
            for (int mt = 0; mt < 4; mt++) ldsm4(a[mt], tA + mt * (16 * 64) + koA);
            #pragma unroll
            for (int nt = 0; nt < 4; nt++) {
                ldsm4(bh[nt], tBh + nt * (16 * 64) + koB);
                ldsm4(bl[nt], tBl + nt * (16 * 64) + koB);
            }
            #pragma unroll
            for (int mi = 0; mi < 4; mi++)
                #pragma unroll
                for (int ni = 0; ni < 8; ni++) {
                    const int g = ni >> 1, o = (ni & 1) * 2;
                    mma16816(acc[mi][ni], a[mi], bh[g][o], bh[g][o + 1]);  // A*Bh
                    mma16816(acc[mi][ni], a[mi], bl[g][o], bl[g][o + 1]);  // A*Bl
                }
        }
    }

    const int gid = lane >> 2;
    const int tig = lane & 3;

    auto storePair = [&](int m, int n, float v0, float v1) {
        if (bias) { v0 += bias[n]; v1 += bias[n + 1]; }
        if (mode == 0) {
            float2 t; t.x = v0; t.y = v1;
            *reinterpret_cast<float2*>(&outF[(size_t)m * Ntot + n]) = t;
        } else {
            const int p  = n >> 11;                 // 0=q, 1=k, 2=v
            const int n2 = n & (HIDDEN - 1);
            const int b = m >> 11, s = m & (SSEQ - 1);
            const int h = n2 >> 7, d = n2 & (HDIM - 1);
            const size_t idx = (((size_t)(b * NHEAD + h) * SSEQ) + s) * HDIM + d;
            const __half h0 = __float2half_rn(v0);
            const __half h1 = __float2half_rn(v1);
            __half2 th; th.x = h0; th.y = h1;
            if (p == 0) {
                *reinterpret_cast<__half2*>(&oq[idx]) = th;
            } else {
                __half* oh = (p == 1) ? okh : ovh;
                __half* ol = (p == 1) ? okl : ovl;
                __half2 tl;
                tl.x = __float2half_rn(v0 - __half2float(h0));
                tl.y = __float2half_rn(v1 - __half2float(h1));
                *reinterpret_cast<__half2*>(&oh[idx]) = th;
                *reinterpret_cast<__half2*>(&ol[idx]) = tl;
            }
        }
    };

    #pragma unroll
    for (int mi = 0; mi < 4; mi++) {
        #pragma unroll
        for (int ni = 0; ni < 8; ni++) {
            const int m = m0 + wm * 64 + mi * 16 + gid;
            const int n = n0 + wn * 64 + ni * 8 + tig * 2;
            storePair(m,     n, acc[mi][ni][0], acc[mi][ni][1]);
            storePair(m + 8, n, acc[mi][ni][2], acc[mi][ni][3]);
        }
    }
}

// ===================== fused flash attention (fp16x2) =======================
// 64 q-rows/CTA, 128 thr, 32-key stages, 3 stages, 2 CTAs/SM.
// Q single fp16 (A side); K, V fp16 hi/lo (B side).  S = Q*Kh + Q*Kl;
// O += P*Vh + P*Vl with P packed to single fp16.
#define FA_STRIDE  272                       // 128 fp16 + 8 pad
#define FA_KVTILE  (32 * FA_STRIDE)          // 8704
#define FA_STAGE   (4 * FA_KVTILE)           // Kh,Kl,Vh,Vl = 34816
#define FA_SMEM    (3 * FA_STAGE)            // 104448 -> 2 CTAs/SM
#define FA_QTILE   (64 * FA_STRIDE)          // 17408

__global__ void __launch_bounds__(128, 2)
fa_kernel(const __half* __restrict__ q,
          const __half* __restrict__ kh, const __half* __restrict__ kl,
          const __half* __restrict__ vh, const __half* __restrict__ vl,
          const float* __restrict__ mask, __half* __restrict__ ao)
{
    extern __shared__ __align__(128) char smem[];
    const uint32_t sb   = smem_to_u32(smem);
    const uint32_t sStg = sb;

    const int tid  = threadIdx.x;
    const int lane = tid & 31;
    const int wid  = tid >> 5;           // 0..3
    const int gid  = lane >> 2;
    const int tig  = lane & 3;

    const int z  = blockIdx.y;
    const int q0 = blockIdx.x * 64;
    const int b  = z >> 4;
    const int h  = z & (NHEAD - 1);

    const size_t qBase  = ((size_t)z * SSEQ + q0) * HDIM;
    const size_t kvBase = (size_t)z * SSEQ * HDIM;

    // ---- Q tile (64 rows, single fp16) into stage buf 2, then to registers
    const uint32_t sQ = sStg + 2 * FA_STAGE;
    #pragma unroll
    for (int ii = 0; ii < 8; ii++) {
        const int i = tid + ii * 128;            // 0..1023
        const int r = i >> 4;                    // 0..63
        const int c = i & 15;
        const uint32_t so = (uint32_t)(r * FA_STRIDE + c * 16);
        const size_t go = qBase + (size_t)r * HDIM + c * 8;
        CP_ASYNC16(sQ + so, (const char*)(q + go));
    }
    CP_ASYNC_COMMIT();                       // group: Q

    auto load_stage = [&](int st, int k0) {
        const uint32_t tb = sStg + st * FA_STAGE;
        #pragma unroll
        for (int ii = 0; ii < 4; ii++) {
            const int i = tid + ii * 128;        // 0..511
            const int r = i >> 4;                // 0..31
            const int c = i & 15;
            const uint32_t so = (uint32_t)(r * FA_STRIDE + c * 16);
            const size_t go = kvBase + (size_t)(k0 + r) * HDIM + c * 8;
            CP_ASYNC16(tb + 0 * FA_KVTILE + so, (const char*)(kh + go));
            CP_ASYNC16(tb + 1 * FA_KVTILE + so, (const char*)(kl + go));
            CP_ASYNC16(tb + 2 * FA_KVTILE + so, (const char*)(vh + go));
            CP_ASYNC16(tb + 3 * FA_KVTILE + so, (const char*)(vl + go));
        }
        CP_ASYNC_COMMIT();
    };
    load_stage(0, 0);
    load_stage(1, 32);

    // Q fragments -> registers
    const uint32_t aOff = (uint32_t)((16 * wid + (lane & 15)) * FA_STRIDE + (lane >> 4) * 16);
    uint32_t qA[8][4];
    CP_ASYNC_WAIT(2);
    __syncthreads();
    #pragma unroll
    for (int kd = 0; kd < 8; kd++)
        ldsm4(qA[kd], sQ + aOff + kd * 32);

    float O[16][4];
    #pragma unroll
    for (int i = 0; i < 16; i++)
        #pragma unroll
        for (int j = 0; j < 4; j++) O[i][j] = 0.0f;
    float m0 = -1e30f, m1 = -1e30f, l0 = 0.0f, l1 = 0.0f;

    const uint32_t bOff = (uint32_t)(((lane & 7) + ((lane >> 4) & 1) * 8) * FA_STRIDE
                                     + ((lane >> 3) & 1) * 16);
    const uint32_t vOff = (uint32_t)(((lane & 7) + ((lane >> 3) & 1) * 8) * FA_STRIDE
                                     + ((lane >> 4) & 1) * 16);
    const float* mrow = mask + (size_t)b * SSEQ;
    const float LOG2E  = 1.4426950408889634f;
    const float scale2 = 0.08838834764831845f * LOG2E;   // (1/sqrt(128))*log2(e)

    for (int c = 0; c < 64; c++) {
        if (c + 1 < 64) { CP_ASYNC_WAIT(1); } else { CP_ASYNC_WAIT(0); }
        __syncthreads();
        if (c + 2 < 64) load_stage((c + 2) % 3, (c + 2) * 32);

        const uint32_t tb = sStg + (c % 3) * FA_STAGE;
        const int k0 = c * 32;

        float S[4][4];
        #pragma unroll
        for (int i = 0; i < 4; i++)
            #pragma unroll
            for (int j = 0; j < 4; j++) S[i][j] = 0.0f;

        #pragma unroll
        for (int kd = 0; kd < 8; kd++) {
            #pragma unroll
            for (int np = 0; np < 2; np++) {
                uint32_t bH[4], bL[4];
                ldsm4(bH, tb + 0 * FA_KVTILE + bOff + np * (16 * FA_STRIDE) + kd * 32);
                ldsm4(bL, tb + 1 * FA_KVTILE + bOff + np * (16 * FA_STRIDE) + kd * 32);
                mma16816(S[2 * np],     qA[kd], bH[0], bH[1]);
                mma16816(S[2 * np],     qA[kd], bL[0], bL[1]);
                mma16816(S[2 * np + 1], qA[kd], bH[2], bH[3]);
                mma16816(S[2 * np + 1], qA[kd], bL[2], bL[3]);
            }
        }

        // ---- scale + mask (log2 domain)
        #pragma unroll
        for (int nt = 0; nt < 4; nt++) {
            const float2 mv = *reinterpret_cast<const float2*>(mrow + k0 + nt * 8 + 2 * tig);
            const float mx2 = mv.x * LOG2E;
            const float my2 = mv.y * LOG2E;
            S[nt][0] = fmaf(S[nt][0], scale2, mx2);
            S[nt][1] = fmaf(S[nt][1], scale2, my2);
            S[nt][2] = fmaf(S[nt][2], scale2, mx2);
            S[nt][3] = fmaf(S[nt][3], scale2, my2);
        }

        float mx0 = -1e30f, mx1 = -1e30f;
        #pragma unroll
        for (int nt = 0; nt < 4; nt++) {
            mx0 = fmaxf(mx0, fmaxf(S[nt][0], S[nt][1]));
            mx1 = fmaxf(mx1, fmaxf(S[nt][2], S[nt][3]));
        }
        mx0 = fmaxf(mx0, __shfl_xor_sync(0xFFFFFFFFu, mx0, 1));
        mx0 = fmaxf(mx0, __shfl_xor_sync(0xFFFFFFFFu, mx0, 2));
        mx1 = fmaxf(mx1, __shfl_xor_sync(0xFFFFFFFFu, mx1, 1));
        mx1 = fmaxf(mx1, __shfl_xor_sync(0xFFFFFFFFu, mx1, 2));

        const float nm0 = fmaxf(m0, mx0);
        const float nm1 = fmaxf(m1, mx1);
        const float ef0 = fast_exp2(m0 - nm0);
        const float ef1 = fast_exp2(m1 - nm1);

        float rs0 = 0.0f, rs1 = 0.0f;
        #pragma unroll
        for (int nt = 0; nt < 4; nt++) {
            S[nt][0] = fast_exp2(S[nt][0] - nm0);
            S[nt][1] = fast_exp2(S[nt][1] - nm0);
            S[nt][2] = fast_exp2(S[nt][2] - nm1);
            S[nt][3] = fast_exp2(S[nt][3] - nm1);
            rs0 += S[nt][0] + S[nt][1];
            rs1 += S[nt][2] + S[nt][3];
        }
        rs0 += __shfl_xor_sync(0xFFFFFFFFu, rs0, 1);
        rs0 += __shfl_xor_sync(0xFFFFFFFFu, rs0, 2);
        rs1 += __shfl_xor_sync(0xFFFFFFFFu, rs1, 1);
        rs1 += __shfl_xor_sync(0xFFFFFFFFu, rs1, 2);

        l0 = l0 * ef0 + rs0;
        l1 = l1 * ef1 + rs1;
        m0 = nm0; m1 = nm1;

        #pragma unroll
        for (int nt = 0; nt < 16; nt++) {
            O[nt][0] *= ef0; O[nt][1] *= ef0;
            O[nt][2] *= ef1; O[nt][3] *= ef1;
        }

        // ---- P (single fp16) @ (Vh + Vl)
        #pragma unroll
        for (int ks = 0; ks < 2; ks++) {
            uint32_t paH[4];
            #pragma unroll
            for (int qq = 0; qq < 2; qq++) {
                const float* s4 = S[2 * ks + qq];
                paH[qq * 2 + 0] = pack_half2(s4[0], s4[1]);
                paH[qq * 2 + 1] = pack_half2(s4[2], s4[3]);
            }
            #pragma unroll
            for (int ntp = 0; ntp < 8; ntp++) {
                uint32_t vH[4], vL[4];
                ldsm4t(vH, tb + 2 * FA_KVTILE + vOff + ks * (16 * FA_STRIDE) + ntp * 32);
                ldsm4t(vL, tb + 3 * FA_KVTILE + vOff + ks * (16 * FA_STRIDE) + ntp * 32);
                mma16816(O[2 * ntp],     paH, vH[0], vH[1]);
                mma16816(O[2 * ntp],     paH, vL[0], vL[1]);
                mma16816(O[2 * ntp + 1], paH, vH[2], vH[3]);
                mma16816(O[2 * ntp + 1], paH, vL[2], vL[3]);
            }
        }
    }

    const float inv0 = 1.0f / l0;
    const float inv1 = 1.0f / l1;
    const int r0 = q0 + 16 * wid + gid;
    const int r1 = r0 + 8;
    #pragma unroll
    for (int nt = 0; nt < 16; nt++) {
        const int d = h * HDIM + nt * 8 + 2 * tig;
        const size_t i0 = ((size_t)b * SSEQ + r0) * HIDDEN + d;
        const size_t i1 = ((size_t)b * SSEQ + r1) * HIDDEN + d;
        __half2 t0, t1;
        t0.x = __float2half_rn(O[nt][0] * inv0);
        t0.y = __float2half_rn(O[nt][1] * inv0);
        t1.x = __float2half_rn(O[nt][2] * inv1);
        t1.y = __float2half_rn(O[nt][3] * inv1);
        *reinterpret_cast<__half2*>(&ao[i0]) = t0;
        *reinterpret_cast<__half2*>(&ao[i1]) = t1;
    }
}

// ===================== fp32 -> fp16 conversions =============================
// single fp16 (A-side operands)
__global__ void __launch_bounds__(256)
cvt_fp16(const float* __restrict__ in, __half* __restrict__ out, int n4)
{
    const int i = blockIdx.x * 256 + threadIdx.x;
    if (i >= n4) return;
    const float4 v = reinterpret_cast<const float4*>(in)[i];
    union { __half b[4]; uint2 u; } H;
    H.b[0] = __float2half_rn(v.x);
    H.b[1] = __float2half_rn(v.y);
    H.b[2] = __float2half_rn(v.z);
    H.b[3] = __float2half_rn(v.w);
    reinterpret_cast<uint2*>(out)[i] = H.u;
}

// 4 weight matrices in one launch (hi/lo fp16): blockIdx.y selects Wq/Wk/Wv/Wo.
__global__ void __launch_bounds__(256)
split_fp16_w4(const float* __restrict__ w0, const float* __restrict__ w1,
              const float* __restrict__ w2, const float* __restrict__ w3,
              __half* __restrict__ w3h, __half* __restrict__ w3l,
              __half* __restrict__ woh, __half* __restrict__ wol,
              int n4)
{
    const int i = blockIdx.x * 256 + threadIdx.x;
    if (i >= n4) return;
    const int p = blockIdx.y;
    const float* in = (p == 0) ? w0 : (p == 1) ? w1 : (p == 2) ? w2 : w3;
    const size_t wOff = (size_t)HIDDEN * HIDDEN / 4;   // in uint2 units
    __half* hi;
    __half* lo;
    size_t o;
    if (p < 3) { hi = w3h; lo = w3l; o = (size_t)p * wOff; }
    else       { hi = woh; lo = wol; o = 0; }

    const float4 v = reinterpret_cast<const float4*>(in)[i];
    union { __half b[4]; uint2 u; } H, L;
    H.b[0] = __float2half_rn(v.x);
    H.b[1] = __float2half_rn(v.y);
    H.b[2] = __float2half_rn(v.z);
    H.b[3] = __float2half_rn(v.w);
    L.b[0] = __float2half_rn(v.x - __half2float(H.b[0]));
    L.b[1] = __float2half_rn(v.y - __half2float(H.b[1]));
    L.b[2] = __float2half_rn(v.z - __half2float(H.b[2]));
    L.b[3] = __float2half_rn(v.w - __half2float(H.b[3]));
    reinterpret_cast<uint2*>(hi)[o + i] = H.u;
    reinterpret_cast<uint2*>(lo)[o + i] = L.u;
}

// bias concat: [bq | bk | bv]
__global__ void __launch_bounds__(256)
concat_bias(const float* __restrict__ a, const float* __restrict__ b,
            const float* __restrict__ c, float* __restrict__ o)
{
    const int i = blockIdx.x * 256 + threadIdx.x;
    if (i < HIDDEN)          o[i] = a[i];
    else if (i < 2 * HIDDEN) o[i] = b[i - HIDDEN];
    else if (i < 3 * HIDDEN) o[i] = c[i - 2 * HIDDEN];
}

// ---------------------------------------------------------------------------
extern "C" void kernel_launch(void* const* d_in, const int* in_sizes, int n_in,
                              void* d_out, int out_size)
{
    (void)in_sizes; (void)n_in; (void)out_size;
    const float* x    = (const float*)d_in[0];
    const float* mask = (const float*)d_in[1];
    const float* Wq   = (const float*)d_in[2];
    const float* bq   = (const float*)d_in[3];
    const float* Wk   = (const float*)d_in[4];
    const float* bk   = (const float*)d_in[5];
    const float* Wv   = (const float*)d_in[6];
    const float* bv   = (const float*)d_in[7];
    const float* Wo   = (const float*)d_in[8];
    const float* bo   = (const float*)d_in[9];
    float* out = (float*)d_out;

    __half *xs, *w3h, *w3l, *woh, *wol;
    __half *qs, *khp, *klp, *vhp, *vlp, *aos;
    float* b3;
    cudaGetSymbolAddress((void**)&xs,  g_x);
    cudaGetSymbolAddress((void**)&w3h, g_w3h);
    cudaGetSymbolAddress((void**)&w3l, g_w3l);
    cudaGetSymbolAddress((void**)&woh, g_woh);
    cudaGetSymbolAddress((void**)&wol, g_wol);
    cudaGetSymbolAddress((void**)&b3,  g_b3);
    cudaGetSymbolAddress((void**)&qs,  g_q);
    cudaGetSymbolAddress((void**)&khp, g_kh);
    cudaGetSymbolAddress((void**)&klp, g_kl);
    cudaGetSymbolAddress((void**)&vhp, g_vh);
    cudaGetSymbolAddress((void**)&vlp, g_vl);
    cudaGetSymbolAddress((void**)&aos, g_ao);

    cudaFuncSetAttribute(tgemm_nt, cudaFuncAttributeMaxDynamicSharedMemorySize,
                         TG_SMEM);
    cudaFuncSetAttribute(fa_kernel, cudaFuncAttributeMaxDynamicSharedMemorySize,
                         FA_SMEM);

    // ---- conversions
    const int nX4 = (MROWS * HIDDEN) / 4;
    const int nW4 = (HIDDEN * HIDDEN) / 4;
    cvt_fp16<<<nX4 / 256, 256>>>(x, xs, nX4);
    split_fp16_w4<<<dim3(nW4 / 256, 4), 256>>>(Wq, Wk, Wv, Wo,
                                               w3h, w3l, woh, wol, nW4);
    concat_bias<<<(3 * HIDDEN) / 256, 256>>>(bq, bk, bv, b3);

    // ---- fused QKV projection -> q single; k, v hi/lo  [B,H,S,D]
    const dim3 gQKV(3 * HIDDEN / 128, MROWS / 128, 1);   // (48, 32)
    tgemm_nt<<<gQKV, 128, TG_SMEM>>>(xs, w3h, w3l, b3, HIDDEN, 3 * HIDDEN, 1,
                                     nullptr, qs, khp, klp, vhp, vlp);

    // ---- fused attention -> AO single fp16 [B,S,HIDDEN]
    const dim3 gFA(SSEQ / 64, BH, 1);   // (32, 32) = 1024 CTAs
    fa_kernel<<<gFA, 128, FA_SMEM>>>(qs, khp, klp, vhp, vlp, mask, aos);

    // ---- output projection (+bias) -> d_out
    const dim3 gO(HIDDEN / 128, MROWS / 128, 1);
    tgemm_nt<<<gO, 128, TG_SMEM>>>(aos, woh, wol, bo, HIDDEN, HIDDEN, 0,
                                   out, nullptr, nullptr, nullptr, nullptr,
                                   nullptr);
}

// round 15
// speedup vs baseline: 1.6558x; 1.2175x over previous
#include <cuda_runtime.h>
#include <cuda_fp16.h>
#include <math.h>
#include <stdint.h>

// Problem constants
#define HIDDEN 2048
#define NHEAD  16
#define HDIM   128
#define BB     2
#define SSEQ   2048
#define BH     (BB * NHEAD)      // 32
#define MROWS  (BB * SSEQ)       // 4096

// ---------------- scratch (device globals; no allocation allowed) -----------
__device__ __align__(128) __half g_x  [(size_t)MROWS * HIDDEN];              // fp16 single
__device__ __align__(128) __half g_w3h[(size_t)3 * HIDDEN * HIDDEN];         // Wq|Wk|Wv hi
__device__ __align__(128) __half g_w3l[(size_t)3 * HIDDEN * HIDDEN];         // lo
__device__ __align__(128) __half g_woh[(size_t)HIDDEN * HIDDEN];
__device__ __align__(128) __half g_wol[(size_t)HIDDEN * HIDDEN];
__device__ __align__(128) float  g_b3 [3 * HIDDEN];                          // bq|bk|bv
__device__ __align__(128) __half g_q  [(size_t)BH * SSEQ * HDIM];  // [B,H,S,D] single
__device__ __align__(128) __half g_k  [(size_t)BH * SSEQ * HDIM];  // single
__device__ __align__(128) __half g_v  [(size_t)BH * SSEQ * HDIM];  // single
__device__ __align__(128) __half g_ao [(size_t)MROWS * HIDDEN];              // single

// ============================ PTX helpers ====================================
__device__ __forceinline__ uint32_t smem_to_u32(const void* smem_ptr) {
    uint32_t addr;
    asm("{ .reg .u64 tmp; cvta.to.shared.u64 tmp, %1; cvt.u32.u64 %0, tmp; }"
        : "=r"(addr) : "l"(smem_ptr));
    return addr;
}
#define CP_ASYNC16(smem_u32, gptr) \
    asm volatile("cp.async.cg.shared.global [%0], [%1], 16;" \
        :: "r"((uint32_t)(smem_u32)), "l"(gptr) : "memory")
#define CP_ASYNC_COMMIT() asm volatile("cp.async.commit_group;" ::: "memory")
#define CP_ASYNC_WAIT(n)  asm volatile("cp.async.wait_group %0;" :: "n"(n) : "memory")

__device__ __forceinline__ void ldsm4(uint32_t* r, uint32_t addr) {
    asm volatile("ldmatrix.sync.aligned.m8n8.x4.shared.b16 {%0,%1,%2,%3}, [%4];"
        : "=r"(r[0]), "=r"(r[1]), "=r"(r[2]), "=r"(r[3]) : "r"(addr));
}
__device__ __forceinline__ void ldsm4t(uint32_t* r, uint32_t addr) {
    asm volatile("ldmatrix.sync.aligned.m8n8.x4.trans.shared.b16 {%0,%1,%2,%3}, [%4];"
        : "=r"(r[0]), "=r"(r[1]), "=r"(r[2]), "=r"(r[3]) : "r"(addr));
}
// fp16 inputs, fp32 accumulate
__device__ __forceinline__ void mma16816(float* d, const uint32_t* a,
                                         uint32_t b0, uint32_t b1) {
    asm volatile(
        "mma.sync.aligned.m16n8k16.row.col.f32.f16.f16.f32 "
        "{%0,%1,%2,%3}, {%4,%5,%6,%7}, {%8,%9}, {%0,%1,%2,%3};"
        : "+f"(d[0]), "+f"(d[1]), "+f"(d[2]), "+f"(d[3])
        : "r"(a[0]), "r"(a[1]), "r"(a[2]), "r"(a[3]), "r"(b0), "r"(b1));
}
__device__ __forceinline__ float fast_exp2(float x) {
    float y;
    asm("ex2.approx.f32 %0, %1;" : "=f"(y) : "f"(x));
    return y;
}
__device__ __forceinline__ uint32_t pack_half2(float a, float b) {
    __half2 t; t.x = __float2half_rn(a); t.y = __float2half_rn(b);
    return *reinterpret_cast<uint32_t*>(&t);
}

// ===================== HMMA fp16x2 NT GEMM ==================================
// C = A @ (Bh+Bl)^T (+bias).  A: [M,K] fp16 single, B*: [Ntot,K] fp16 hi/lo.
// CTA 128x128, 4 warps of 64x64, K-chunk 32, XOR swizzle, 4-stage single-sync
// pipeline (prefetch depth 3), 2 CTAs/SM.
// mode 0: fp32 C[m*Ntot+n]
// mode 1: fused-QKV scatter [B,H,S,D], all outputs single fp16 (q, k, v).
#define TG_TILE     (128 * 64)              // 8192
#define TG_STAGE    (3 * TG_TILE)           // A, Bh, Bl = 24576
#define TG_SMEM     (4 * TG_STAGE)          // 98304 -> 2 CTAs/SM

__global__ void __launch_bounds__(128, 2)
tgemm_nt(const __half* __restrict__ A,
         const __half* __restrict__ Bh, const __half* __restrict__ Bl,
         const float* __restrict__ bias, int K, int Ntot, int mode,
         float* __restrict__ outF,
         __half* __restrict__ oq, __half* __restrict__ ok,
         __half* __restrict__ ov)
{
    extern __shared__ __align__(128) char smem[];
    const uint32_t sb = smem_to_u32(smem);

    const int tid  = threadIdx.x;
    const int lane = tid & 31;
    const int wid  = tid >> 5;          // 0..3
    const int wm   = wid >> 1;          // 0..1
    const int wn   = wid & 1;           // 0..1

    const int m0 = blockIdx.y * 128;
    const int n0 = blockIdx.x * 128;
    const int nch = K >> 5;             // K / 32

    const size_t aBase = (size_t)m0 * K;
    const size_t bBase = (size_t)n0 * K;

    float acc[4][8][4];
    #pragma unroll
    for (int i = 0; i < 4; i++)
        #pragma unroll
        for (int j = 0; j < 8; j++)
            #pragma unroll
            for (int t = 0; t < 4; t++) acc[i][j][t] = 0.0f;

    auto load_chunk = [&](int buf, int k0) {
        const uint32_t tb = sb + buf * TG_STAGE;
        #pragma unroll
        for (int ii = 0; ii < 4; ii++) {
            const int i = tid + ii * 128;        // 0..511
            const int r = i >> 2;                // row 0..127
            const int c = i & 3;                 // 16B chunk 0..3
            const uint32_t so = (uint32_t)(r * 64 + ((c ^ ((r >> 1) & 3)) << 4));
            const size_t aOff = aBase + (size_t)r * K + k0 + c * 8;
            const size_t bOff = bBase + (size_t)r * K + k0 + c * 8;
            CP_ASYNC16(tb + 0 * TG_TILE + so, (const char*)(A  + aOff));
            CP_ASYNC16(tb + 1 * TG_TILE + so, (const char*)(Bh + bOff));
            CP_ASYNC16(tb + 2 * TG_TILE + so, (const char*)(Bl + bOff));
        }
        CP_ASYNC_COMMIT();
    };

    const int hiA = lane >> 4;
    const int swA = ((lane & 15) >> 1) & 3;
    const uint32_t aRowOff = (uint32_t)((wm * 64 + (lane & 15)) * 64);
    const int hiB = (lane >> 3) & 1;
    const int swB = ((lane & 7) >> 1) & 3;
    const uint32_t bRowOff = (uint32_t)((wn * 64 + (lane & 7) + ((lane >> 4) & 1) * 8) * 64);

    load_chunk(0, 0);
    if (nch > 1) load_chunk(1, 32);
    if (nch > 2) load_chunk(2, 64);

    for (int c = 0; c < nch; c++) {
        const int buf = c & 3;
        if (c + 2 < nch)      { CP_ASYNC_WAIT(2); }
        else if (c + 1 < nch) { CP_ASYNC_WAIT(1); }
        else                  { CP_ASYNC_WAIT(0); }
        __syncthreads();
        if (c + 3 < nch) load_chunk((c + 3) & 3, (c + 3) * 32);

        const uint32_t tb  = sb + buf * TG_STAGE;
        const uint32_t tA  = tb + 0 * TG_TILE + aRowOff;
        const uint32_t tBh = tb + 1 * TG_TILE + bRowOff;
        const uint32_t tBl = tb + 2 * TG_TILE + bRowOff;

        #pragma unroll
        for (int ks = 0; ks < 2; ks++) {
            const uint32_t koA = (uint32_t)(((ks * 2 + hiA) ^ swA) << 4);
            const uint32_t koB = (uint32_t)(((ks * 2 + hiB) ^ swB) << 4);
            uint32_t a[4][4], bh[4][4], bl[4][4];
            #pragma unroll
            for (int mt = 0; mt < 4; mt++) ldsm4(a[mt], tA + mt * (16 * 64) + koA);
            #pragma unroll
            for (int nt = 0; nt < 4; nt++) {
                ldsm4(bh[nt], tBh + nt * (16 * 64) + koB);
                ldsm4(bl[nt], tBl + nt * (16 * 64) + koB);
            }
            #pragma unroll
            for (int mi = 0; mi < 4; mi++)
                #pragma unroll
                for (int ni = 0; ni < 8; ni++) {
                    const int g = ni >> 1, o = (ni & 1) * 2;
                    mma16816(acc[mi][ni], a[mi], bh[g][o], bh[g][o + 1]);  // A*Bh
                    mma16816(acc[mi][ni], a[mi], bl[g][o], bl[g][o + 1]);  // A*Bl
                }
        }
    }

    const int gid = lane >> 2;
    const int tig = lane & 3;

    auto storePair = [&](int m, int n, float v0, float v1) {
        if (bias) { v0 += bias[n]; v1 += bias[n + 1]; }
        if (mode == 0) {
            float2 t; t.x = v0; t.y = v1;
            *reinterpret_cast<float2*>(&outF[(size_t)m * Ntot + n]) = t;
        } else {
            const int p  = n >> 11;                 // 0=q, 1=k, 2=v
            const int n2 = n & (HIDDEN - 1);
            const int b = m >> 11, s = m & (SSEQ - 1);
            const int h = n2 >> 7, d = n2 & (HDIM - 1);
            const size_t idx = (((size_t)(b * NHEAD + h) * SSEQ) + s) * HDIM + d;
            __half2 th;
            th.x = __float2half_rn(v0);
            th.y = __float2half_rn(v1);
            __half* dst = (p == 0) ? oq : ((p == 1) ? ok : ov);
            *reinterpret_cast<__half2*>(&dst[idx]) = th;
        }
    };

    #pragma unroll
    for (int mi = 0; mi < 4; mi++) {
        #pragma unroll
        for (int ni = 0; ni < 8; ni++) {
            const int m = m0 + wm * 64 + mi * 16 + gid;
            const int n = n0 + wn * 64 + ni * 8 + tig * 2;
            storePair(m,     n, acc[mi][ni][0], acc[mi][ni][1]);
            storePair(m + 8, n, acc[mi][ni][2], acc[mi][ni][3]);
        }
    }
}

// ===================== fused flash attention (plain fp16) ===================
// 64 q-rows/CTA, 128 thr, 32-key stages (K,V single fp16), 3 stages,
// 3 CTAs/SM, Q in registers, log2-domain softmax, fp32 accum.
#define FA_STRIDE  272                       // 128 fp16 + 8 pad
#define FA_KVTILE  (32 * FA_STRIDE)          // 8704
#define FA_STAGE   (2 * FA_KVTILE)           // K, V = 17408
#define FA_SMEM    (3 * FA_STAGE)            // 52224 -> 3 CTAs/SM (regs permitting)
#define FA_QTILE   (64 * FA_STRIDE)          // 17408 (= one stage)

__global__ void __launch_bounds__(128, 3)
fa_kernel(const __half* __restrict__ q,
          const __half* __restrict__ k, const __half* __restrict__ v,
          const float* __restrict__ mask, __half* __restrict__ ao)
{
    extern __shared__ __align__(128) char smem[];
    const uint32_t sb   = smem_to_u32(smem);
    const uint32_t sStg = sb;

    const int tid  = threadIdx.x;
    const int lane = tid & 31;
    const int wid  = tid >> 5;           // 0..3
    const int gid  = lane >> 2;
    const int tig  = lane & 3;

    const int z  = blockIdx.y;
    const int q0 = blockIdx.x * 64;
    const int b  = z >> 4;
    const int h  = z & (NHEAD - 1);

    const size_t qBase  = ((size_t)z * SSEQ + q0) * HDIM;
    const size_t kvBase = (size_t)z * SSEQ * HDIM;

    // ---- Q tile (64 rows) into stage buf 2 (temporarily), then to registers
    const uint32_t sQ = sStg + 2 * FA_STAGE;
    #pragma unroll
    for (int ii = 0; ii < 8; ii++) {
        const int i = tid + ii * 128;            // 0..1023
        const int r = i >> 4;                    // 0..63
        const int c = i & 15;
        const uint32_t so = (uint32_t)(r * FA_STRIDE + c * 16);
        const size_t go = qBase + (size_t)r * HDIM + c * 8;
        CP_ASYNC16(sQ + so, (const char*)(q + go));
    }
    CP_ASYNC_COMMIT();                       // group: Q

    auto load_stage = [&](int st, int k0) {
        const uint32_t tb = sStg + st * FA_STAGE;
        #pragma unroll
        for (int ii = 0; ii < 4; ii++) {
            const int i = tid + ii * 128;        // 0..511
            const int r = i >> 4;                // 0..31
            const int c = i & 15;
            const uint32_t so = (uint32_t)(r * FA_STRIDE + c * 16);
            const size_t go = kvBase + (size_t)(k0 + r) * HDIM + c * 8;
            CP_ASYNC16(tb + 0 * FA_KVTILE + so, (const char*)(k + go));
            CP_ASYNC16(tb + 1 * FA_KVTILE + so, (const char*)(v + go));
        }
        CP_ASYNC_COMMIT();
    };
    load_stage(0, 0);
    load_stage(1, 32);

    // Q fragments -> registers (wait for Q group; 2 KV groups may pend)
    const uint32_t aOff = (uint32_t)((16 * wid + (lane & 15)) * FA_STRIDE + (lane >> 4) * 16);
    uint32_t qA[8][4];
    CP_ASYNC_WAIT(2);
    __syncthreads();
    #pragma unroll
    for (int kd = 0; kd < 8; kd++)
        ldsm4(qA[kd], sQ + aOff + kd * 32);

    float O[16][4];
    #pragma unroll
    for (int i = 0; i < 16; i++)
        #pragma unroll
        for (int j = 0; j < 4; j++) O[i][j] = 0.0f;
    float m0 = -1e30f, m1 = -1e30f, l0 = 0.0f, l1 = 0.0f;

    const uint32_t bOff = (uint32_t)(((lane & 7) + ((lane >> 4) & 1) * 8) * FA_STRIDE
                                     + ((lane >> 3) & 1) * 16);
    const uint32_t vOff = (uint32_t)(((lane & 7) + ((lane >> 3) & 1) * 8) * FA_STRIDE
                                     + ((lane >> 4) & 1) * 16);
    const float* mrow = mask + (size_t)b * SSEQ;
    const float LOG2E  = 1.4426950408889634f;
    const float scale2 = 0.08838834764831845f * LOG2E;   // (1/sqrt(128))*log2(e)

    for (int c = 0; c < 64; c++) {
        if (c + 1 < 64) { CP_ASYNC_WAIT(1); } else { CP_ASYNC_WAIT(0); }
        __syncthreads();
        if (c + 2 < 64) load_stage((c + 2) % 3, (c + 2) * 32);

        const uint32_t tb = sStg + (c % 3) * FA_STAGE;
        const int k0 = c * 32;

        float S[4][4];
        #pragma unroll
        for (int i = 0; i < 4; i++)
            #pragma unroll
            for (int j = 0; j < 4; j++) S[i][j] = 0.0f;

        #pragma unroll
        for (int kd = 0; kd < 8; kd++) {
            #pragma unroll
            for (int np = 0; np < 2; np++) {
                uint32_t bH[4];
                ldsm4(bH, tb + 0 * FA_KVTILE + bOff + np * (16 * FA_STRIDE) + kd * 32);
                mma16816(S[2 * np],     qA[kd], bH[0], bH[1]);
                mma16816(S[2 * np + 1], qA[kd], bH[2], bH[3]);
            }
        }

        // ---- scale + mask (log2 domain)
        #pragma unroll
        for (int nt = 0; nt < 4; nt++) {
            const float2 mv = *reinterpret_cast<const float2*>(mrow + k0 + nt * 8 + 2 * tig);
            const float mx2 = mv.x * LOG2E;
            const float my2 = mv.y * LOG2E;
            S[nt][0] = fmaf(S[nt][0], scale2, mx2);
            S[nt][1] = fmaf(S[nt][1], scale2, my2);
            S[nt][2] = fmaf(S[nt][2], scale2, mx2);
            S[nt][3] = fmaf(S[nt][3], scale2, my2);
        }

        float mx0 = -1e30f, mx1 = -1e30f;
        #pragma unroll
        for (int nt = 0; nt < 4; nt++) {
            mx0 = fmaxf(mx0, fmaxf(S[nt][0], S[nt][1]));
            mx1 = fmaxf(mx1, fmaxf(S[nt][2], S[nt][3]));
        }
        mx0 = fmaxf(mx0, __shfl_xor_sync(0xFFFFFFFFu, mx0, 1));
        mx0 = fmaxf(mx0, __shfl_xor_sync(0xFFFFFFFFu, mx0, 2));
        mx1 = fmaxf(mx1, __shfl_xor_sync(0xFFFFFFFFu, mx1, 1));
        mx1 = fmaxf(mx1, __shfl_xor_sync(0xFFFFFFFFu, mx1, 2));

        const float nm0 = fmaxf(m0, mx0);
        const float nm1 = fmaxf(m1, mx1);
        const float ef0 = fast_exp2(m0 - nm0);
        const float ef1 = fast_exp2(m1 - nm1);

        float rs0 = 0.0f, rs1 = 0.0f;
        #pragma unroll
        for (int nt = 0; nt < 4; nt++) {
            S[nt][0] = fast_exp2(S[nt][0] - nm0);
            S[nt][1] = fast_exp2(S[nt][1] - nm0);
            S[nt][2] = fast_exp2(S[nt][2] - nm1);
            S[nt][3] = fast_exp2(S[nt][3] - nm1);
            rs0 += S[nt][0] + S[nt][1];
            rs1 += S[nt][2] + S[nt][3];
        }
        rs0 += __shfl_xor_sync(0xFFFFFFFFu, rs0, 1);
        rs0 += __shfl_xor_sync(0xFFFFFFFFu, rs0, 2);
        rs1 += __shfl_xor_sync(0xFFFFFFFFu, rs1, 1);
        rs1 += __shfl_xor_sync(0xFFFFFFFFu, rs1, 2);

        l0 = l0 * ef0 + rs0;
        l1 = l1 * ef1 + rs1;
        m0 = nm0; m1 = nm1;

        #pragma unroll
        for (int nt = 0; nt < 16; nt++) {
            O[nt][0] *= ef0; O[nt][1] *= ef0;
            O[nt][2] *= ef1; O[nt][3] *= ef1;
        }

        // ---- P (single fp16) @ V (single fp16)
        #pragma unroll
        for (int ks = 0; ks < 2; ks++) {
            uint32_t paH[4];
            #pragma unroll
            for (int qq = 0; qq < 2; qq++) {
                const float* s4 = S[2 * ks + qq];
                paH[qq * 2 + 0] = pack_half2(s4[0], s4[1]);
                paH[qq * 2 + 1] = pack_half2(s4[2], s4[3]);
            }
            #pragma unroll
            for (int ntp = 0; ntp < 8; ntp++) {
                uint32_t vH[4];
                ldsm4t(vH, tb + 1 * FA_KVTILE + vOff + ks * (16 * FA_STRIDE) + ntp * 32);
                mma16816(O[2 * ntp],     paH, vH[0], vH[1]);
                mma16816(O[2 * ntp + 1], paH, vH[2], vH[3]);
            }
        }
    }

    const float inv0 = 1.0f / l0;
    const float inv1 = 1.0f / l1;
    const int r0 = q0 + 16 * wid + gid;
    const int r1 = r0 + 8;
    #pragma unroll
    for (int nt = 0; nt < 16; nt++) {
        const int d = h * HDIM + nt * 8 + 2 * tig;
        const size_t i0 = ((size_t)b * SSEQ + r0) * HIDDEN + d;
        const size_t i1 = ((size_t)b * SSEQ + r1) * HIDDEN + d;
        __half2 t0, t1;
        t0.x = __float2half_rn(O[nt][0] * inv0);
        t0.y = __float2half_rn(O[nt][1] * inv0);
        t1.x = __float2half_rn(O[nt][2] * inv1);
        t1.y = __float2half_rn(O[nt][3] * inv1);
        *reinterpret_cast<__half2*>(&ao[i0]) = t0;
        *reinterpret_cast<__half2*>(&ao[i1]) = t1;
    }
}

// ===================== fp32 -> fp16 conversions =============================
__global__ void __launch_bounds__(256)
cvt_fp16(const float* __restrict__ in, __half* __restrict__ out, int n4)
{
    const int i = blockIdx.x * 256 + threadIdx.x;
    if (i >= n4) return;
    const float4 v = reinterpret_cast<const float4*>(in)[i];
    union { __half b[4]; uint2 u; } H;
    H.b[0] = __float2half_rn(v.x);
    H.b[1] = __float2half_rn(v.y);
    H.b[2] = __float2half_rn(v.z);
    H.b[3] = __float2half_rn(v.w);
    reinterpret_cast<uint2*>(out)[i] = H.u;
}

// 4 weight matrices in one launch (hi/lo fp16): blockIdx.y selects Wq/Wk/Wv/Wo.
__global__ void __launch_bounds__(256)
split_fp16_w4(const float* __restrict__ w0, const float* __restrict__ w1,
              const float* __restrict__ w2, const float* __restrict__ w3,
              __half* __restrict__ w3h, __half* __restrict__ w3l,
              __half* __restrict__ woh, __half* __restrict__ wol,
              int n4)
{
    const int i = blockIdx.x * 256 + threadIdx.x;
    if (i >= n4) return;
    const int p = blockIdx.y;
    const float* in = (p == 0) ? w0 : (p == 1) ? w1 : (p == 2) ? w2 : w3;
    const size_t wOff = (size_t)HIDDEN * HIDDEN / 4;   // in uint2 units
    __half* hi;
    __half* lo;
    size_t o;
    if (p < 3) { hi = w3h; lo = w3l; o = (size_t)p * wOff; }
    else       { hi = woh; lo = wol; o = 0; }

    const float4 v = reinterpret_cast<const float4*>(in)[i];
    union { __half b[4]; uint2 u; } H, L;
    H.b[0] = __float2half_rn(v.x);
    H.b[1] = __float2half_rn(v.y);
    H.b[2] = __float2half_rn(v.z);
    H.b[3] = __float2half_rn(v.w);
    L.b[0] = __float2half_rn(v.x - __half2float(H.b[0]));
    L.b[1] = __float2half_rn(v.y - __half2float(H.b[1]));
    L.b[2] = __float2half_rn(v.z - __half2float(H.b[2]));
    L.b[3] = __float2half_rn(v.w - __half2float(H.b[3]));
    reinterpret_cast<uint2*>(hi)[o + i] = H.u;
    reinterpret_cast<uint2*>(lo)[o + i] = L.u;
}

// bias concat: [bq | bk | bv]
__global__ void __launch_bounds__(256)
concat_bias(const float* __restrict__ a, const float* __restrict__ b,
            const float* __restrict__ c, float* __restrict__ o)
{
    const int i = blockIdx.x * 256 + threadIdx.x;
    if (i < HIDDEN)          o[i] = a[i];
    else if (i < 2 * HIDDEN) o[i] = b[i - HIDDEN];
    else if (i < 3 * HIDDEN) o[i] = c[i - 2 * HIDDEN];
}

// ---------------------------------------------------------------------------
extern "C" void kernel_launch(void* const* d_in, const int* in_sizes, int n_in,
                              void* d_out, int out_size)
{
    (void)in_sizes; (void)n_in; (void)out_size;
    const float* x    = (const float*)d_in[0];
    const float* mask = (const float*)d_in[1];
    const float* Wq   = (const float*)d_in[2];
    const float* bq   = (const float*)d_in[3];
    const float* Wk   = (const float*)d_in[4];
    const float* bk   = (const float*)d_in[5];
    const float* Wv   = (const float*)d_in[6];
    const float* bv   = (const float*)d_in[7];
    const float* Wo   = (const float*)d_in[8];
    const float* bo   = (const float*)d_in[9];
    float* out = (float*)d_out;

    __half *xs, *w3h, *w3l, *woh, *wol;
    __half *qs, *ks, *vs, *aos;
    float* b3;
    cudaGetSymbolAddress((void**)&xs,  g_x);
    cudaGetSymbolAddress((void**)&w3h, g_w3h);
    cudaGetSymbolAddress((void**)&w3l, g_w3l);
    cudaGetSymbolAddress((void**)&woh, g_woh);
    cudaGetSymbolAddress((void**)&wol, g_wol);
    cudaGetSymbolAddress((void**)&b3,  g_b3);
    cudaGetSymbolAddress((void**)&qs,  g_q);
    cudaGetSymbolAddress((void**)&ks,  g_k);
    cudaGetSymbolAddress((void**)&vs,  g_v);
    cudaGetSymbolAddress((void**)&aos, g_ao);

    cudaFuncSetAttribute(tgemm_nt, cudaFuncAttributeMaxDynamicSharedMemorySize,
                         TG_SMEM);
    cudaFuncSetAttribute(fa_kernel, cudaFuncAttributeMaxDynamicSharedMemorySize,
                         FA_SMEM);

    // ---- conversions
    const int nX4 = (MROWS * HIDDEN) / 4;
    const int nW4 = (HIDDEN * HIDDEN) / 4;
    cvt_fp16<<<nX4 / 256, 256>>>(x, xs, nX4);
    split_fp16_w4<<<dim3(nW4 / 256, 4), 256>>>(Wq, Wk, Wv, Wo,
                                               w3h, w3l, woh, wol, nW4);
    concat_bias<<<(3 * HIDDEN) / 256, 256>>>(bq, bk, bv, b3);

    // ---- fused QKV projection -> q, k, v single fp16 [B,H,S,D]
    const dim3 gQKV(3 * HIDDEN / 128, MROWS / 128, 1);   // (48, 32)
    tgemm_nt<<<gQKV, 128, TG_SMEM>>>(xs, w3h, w3l, b3, HIDDEN, 3 * HIDDEN, 1,
                                     nullptr, qs, ks, vs);

    // ---- fused attention -> AO single fp16 [B,S,HIDDEN]
    const dim3 gFA(SSEQ / 64, BH, 1);   // (32, 32) = 1024 CTAs
    fa_kernel<<<gFA, 128, FA_SMEM>>>(qs, ks, vs, mask, aos);

    // ---- output projection (+bias) -> d_out
    const dim3 gO(HIDDEN / 128, MROWS / 128, 1);
    tgemm_nt<<<gO, 128, TG_SMEM>>>(aos, woh, wol, bo, HIDDEN, HIDDEN, 0,
                                   out, nullptr, nullptr, nullptr);
}

// round 16
// speedup vs baseline: 2.6344x; 1.5910x over previous
#include <cuda_runtime.h>
#include <cuda_fp16.h>
#include <math.h>
#include <stdint.h>

// Problem constants
#define HIDDEN 2048
#define NHEAD  16
#define HDIM   128
#define BB     2
#define SSEQ   2048
#define BH     (BB * NHEAD)      // 32
#define MROWS  (BB * SSEQ)       // 4096

// ---------------- scratch (device globals; no allocation allowed) -----------
__device__ __align__(128) __half g_x  [(size_t)MROWS * HIDDEN];              // fp16
__device__ __align__(128) __half g_w3 [(size_t)3 * HIDDEN * HIDDEN];         // Wq|Wk|Wv
__device__ __align__(128) __half g_wo [(size_t)HIDDEN * HIDDEN];
__device__ __align__(128) float  g_b3 [3 * HIDDEN];                          // bq|bk|bv
__device__ __align__(128) __half g_q  [(size_t)BH * SSEQ * HDIM];  // [B,H,S,D]
__device__ __align__(128) __half g_k  [(size_t)BH * SSEQ * HDIM];
__device__ __align__(128) __half g_v  [(size_t)BH * SSEQ * HDIM];
__device__ __align__(128) __half g_ao [(size_t)MROWS * HIDDEN];

// ============================ PTX helpers ====================================
__device__ __forceinline__ uint32_t smem_to_u32(const void* smem_ptr) {
    uint32_t addr;
    asm("{ .reg .u64 tmp; cvta.to.shared.u64 tmp, %1; cvt.u32.u64 %0, tmp; }"
        : "=r"(addr) : "l"(smem_ptr));
    return addr;
}
#define CP_ASYNC16(smem_u32, gptr) \
    asm volatile("cp.async.cg.shared.global [%0], [%1], 16;" \
        :: "r"((uint32_t)(smem_u32)), "l"(gptr) : "memory")
#define CP_ASYNC_COMMIT() asm volatile("cp.async.commit_group;" ::: "memory")
#define CP_ASYNC_WAIT(n)  asm volatile("cp.async.wait_group %0;" :: "n"(n) : "memory")

__device__ __forceinline__ void ldsm4(uint32_t* r, uint32_t addr) {
    asm volatile("ldmatrix.sync.aligned.m8n8.x4.shared.b16 {%0,%1,%2,%3}, [%4];"
        : "=r"(r[0]), "=r"(r[1]), "=r"(r[2]), "=r"(r[3]) : "r"(addr));
}
__device__ __forceinline__ void ldsm4t(uint32_t* r, uint32_t addr) {
    asm volatile("ldmatrix.sync.aligned.m8n8.x4.trans.shared.b16 {%0,%1,%2,%3}, [%4];"
        : "=r"(r[0]), "=r"(r[1]), "=r"(r[2]), "=r"(r[3]) : "r"(addr));
}
// fp16 inputs, fp32 accumulate
__device__ __forceinline__ void mma16816(float* d, const uint32_t* a,
                                         uint32_t b0, uint32_t b1) {
    asm volatile(
        "mma.sync.aligned.m16n8k16.row.col.f32.f16.f16.f32 "
        "{%0,%1,%2,%3}, {%4,%5,%6,%7}, {%8,%9}, {%0,%1,%2,%3};"
        : "+f"(d[0]), "+f"(d[1]), "+f"(d[2]), "+f"(d[3])
        : "r"(a[0]), "r"(a[1]), "r"(a[2]), "r"(a[3]), "r"(b0), "r"(b1));
}
__device__ __forceinline__ float fast_exp2(float x) {
    float y;
    asm("ex2.approx.f32 %0, %1;" : "=f"(y) : "f"(x));
    return y;
}
__device__ __forceinline__ uint32_t pack_half2(float a, float b) {
    __half2 t; t.x = __float2half_rn(a); t.y = __float2half_rn(b);
    return *reinterpret_cast<uint32_t*>(&t);
}

// ===================== HMMA fp16 NT GEMM ====================================
// C = A @ B^T (+bias).  A: [M,K] fp16, B: [Ntot,K] fp16, fp32 accumulate.
// CTA 128x128, 4 warps of 64x64, K-chunk 32, XOR swizzle, 4-stage single-sync
// pipeline (prefetch depth 3), 2 CTAs/SM.
// mode 0: fp32 C[m*Ntot+n]
// mode 1: fused-QKV scatter [B,H,S,D], outputs single fp16 (q, k, v).
#define TG_TILE     (128 * 64)              // 8192
#define TG_STAGE    (2 * TG_TILE)           // A, B = 16384
#define TG_SMEM     (4 * TG_STAGE)          // 65536 -> 2 CTAs/SM

__global__ void __launch_bounds__(128, 2)
tgemm_nt(const __half* __restrict__ A, const __half* __restrict__ B,
         const float* __restrict__ bias, int K, int Ntot, int mode,
         float* __restrict__ outF,
         __half* __restrict__ oq, __half* __restrict__ ok,
         __half* __restrict__ ov)
{
    extern __shared__ __align__(128) char smem[];
    const uint32_t sb = smem_to_u32(smem);

    const int tid  = threadIdx.x;
    const int lane = tid & 31;
    const int wid  = tid >> 5;          // 0..3
    const int wm   = wid >> 1;          // 0..1
    const int wn   = wid & 1;           // 0..1

    const int m0 = blockIdx.y * 128;
    const int n0 = blockIdx.x * 128;
    const int nch = K >> 5;             // K / 32

    const size_t aBase = (size_t)m0 * K;
    const size_t bBase = (size_t)n0 * K;

    float acc[4][8][4];
    #pragma unroll
    for (int i = 0; i < 4; i++)
        #pragma unroll
        for (int j = 0; j < 8; j++)
            #pragma unroll
            for (int t = 0; t < 4; t++) acc[i][j][t] = 0.0f;

    auto load_chunk = [&](int buf, int k0) {
        const uint32_t tb = sb + buf * TG_STAGE;
        #pragma unroll
        for (int ii = 0; ii < 4; ii++) {
            const int i = tid + ii * 128;        // 0..511
            const int r = i >> 2;                // row 0..127
            const int c = i & 3;                 // 16B chunk 0..3
            const uint32_t so = (uint32_t)(r * 64 + ((c ^ ((r >> 1) & 3)) << 4));
            const size_t aOff = aBase + (size_t)r * K + k0 + c * 8;
            const size_t bOff = bBase + (size_t)r * K + k0 + c * 8;
            CP_ASYNC16(tb + 0 * TG_TILE + so, (const char*)(A + aOff));
            CP_ASYNC16(tb + 1 * TG_TILE + so, (const char*)(B + bOff));
        }
        CP_ASYNC_COMMIT();
    };

    const int hiA = lane >> 4;
    const int swA = ((lane & 15) >> 1) & 3;
    const uint32_t aRowOff = (uint32_t)((wm * 64 + (lane & 15)) * 64);
    const int hiB = (lane >> 3) & 1;
    const int swB = ((lane & 7) >> 1) & 3;
    const uint32_t bRowOff = (uint32_t)((wn * 64 + (lane & 7) + ((lane >> 4) & 1) * 8) * 64);

    load_chunk(0, 0);
    if (nch > 1) load_chunk(1, 32);
    if (nch > 2) load_chunk(2, 64);

    for (int c = 0; c < nch; c++) {
        const int buf = c & 3;
        if (c + 2 < nch)      { CP_ASYNC_WAIT(2); }
        else if (c + 1 < nch) { CP_ASYNC_WAIT(1); }
        else                  { CP_ASYNC_WAIT(0); }
        __syncthreads();
        if (c + 3 < nch) load_chunk((c + 3) & 3, (c + 3) * 32);

        const uint32_t tb = sb + buf * TG_STAGE;
        const uint32_t tA = tb + 0 * TG_TILE + aRowOff;
        const uint32_t tB = tb + 1 * TG_TILE + bRowOff;

        #pragma unroll
        for (int ks = 0; ks < 2; ks++) {
            const uint32_t koA = (uint32_t)(((ks * 2 + hiA) ^ swA) << 4);
            const uint32_t koB = (uint32_t)(((ks * 2 + hiB) ^ swB) << 4);
            uint32_t a[4][4], bh[4][4];
            #pragma unroll
            for (int mt = 0; mt < 4; mt++) ldsm4(a[mt], tA + mt * (16 * 64) + koA);
            #pragma unroll
            for (int nt = 0; nt < 4; nt++) ldsm4(bh[nt], tB + nt * (16 * 64) + koB);
            #pragma unroll
            for (int mi = 0; mi < 4; mi++)
                #pragma unroll
                for (int ni = 0; ni < 8; ni++) {
                    const int g = ni >> 1, o = (ni & 1) * 2;
                    mma16816(acc[mi][ni], a[mi], bh[g][o], bh[g][o + 1]);
                }
        }
    }

    const int gid = lane >> 2;
    const int tig = lane & 3;

    auto storePair = [&](int m, int n, float v0, float v1) {
        if (bias) { v0 += bias[n]; v1 += bias[n + 1]; }
        if (mode == 0) {
            float2 t; t.x = v0; t.y = v1;
            *reinterpret_cast<float2*>(&outF[(size_t)m * Ntot + n]) = t;
        } else {
            const int p  = n >> 11;                 // 0=q, 1=k, 2=v
            const int n2 = n & (HIDDEN - 1);
            const int b = m >> 11, s = m & (SSEQ - 1);
            const int h = n2 >> 7, d = n2 & (HDIM - 1);
            const size_t idx = (((size_t)(b * NHEAD + h) * SSEQ) + s) * HDIM + d;
            __half2 th;
            th.x = __float2half_rn(v0);
            th.y = __float2half_rn(v1);
            __half* dst = (p == 0) ? oq : ((p == 1) ? ok : ov);
            *reinterpret_cast<__half2*>(&dst[idx]) = th;
        }
    };

    #pragma unroll
    for (int mi = 0; mi < 4; mi++) {
        #pragma unroll
        for (int ni = 0; ni < 8; ni++) {
            const int m = m0 + wm * 64 + mi * 16 + gid;
            const int n = n0 + wn * 64 + ni * 8 + tig * 2;
            storePair(m,     n, acc[mi][ni][0], acc[mi][ni][1]);
            storePair(m + 8, n, acc[mi][ni][2], acc[mi][ni][3]);
        }
    }
}

// ===================== fused flash attention (plain fp16) ===================
// 64 q-rows/CTA, 128 thr, 32-key stages (K,V single fp16), 3 stages,
// 3 CTAs/SM, Q in registers, log2-domain softmax, fp32 accum.
#define FA_STRIDE  272                       // 128 fp16 + 8 pad
#define FA_KVTILE  (32 * FA_STRIDE)          // 8704
#define FA_STAGE   (2 * FA_KVTILE)           // K, V = 17408
#define FA_SMEM    (3 * FA_STAGE)            // 52224 -> 3 CTAs/SM
#define FA_QTILE   (64 * FA_STRIDE)          // 17408 (= one stage)

__global__ void __launch_bounds__(128, 3)
fa_kernel(const __half* __restrict__ q,
          const __half* __restrict__ k, const __half* __restrict__ v,
          const float* __restrict__ mask, __half* __restrict__ ao)
{
    extern __shared__ __align__(128) char smem[];
    const uint32_t sb   = smem_to_u32(smem);
    const uint32_t sStg = sb;

    const int tid  = threadIdx.x;
    const int lane = tid & 31;
    const int wid  = tid >> 5;           // 0..3
    const int gid  = lane >> 2;
    const int tig  = lane & 3;

    const int z  = blockIdx.y;
    const int q0 = blockIdx.x * 64;
    const int b  = z >> 4;
    const int h  = z & (NHEAD - 1);

    const size_t qBase  = ((size_t)z * SSEQ + q0) * HDIM;
    const size_t kvBase = (size_t)z * SSEQ * HDIM;

    // ---- Q tile (64 rows) into stage buf 2 (temporarily), then to registers
    const uint32_t sQ = sStg + 2 * FA_STAGE;
    #pragma unroll
    for (int ii = 0; ii < 8; ii++) {
        const int i = tid + ii * 128;            // 0..1023
        const int r = i >> 4;                    // 0..63
        const int c = i & 15;
        const uint32_t so = (uint32_t)(r * FA_STRIDE + c * 16);
        const size_t go = qBase + (size_t)r * HDIM + c * 8;
        CP_ASYNC16(sQ + so, (const char*)(q + go));
    }
    CP_ASYNC_COMMIT();                       // group: Q

    auto load_stage = [&](int st, int k0) {
        const uint32_t tb = sStg + st * FA_STAGE;
        #pragma unroll
        for (int ii = 0; ii < 4; ii++) {
            const int i = tid + ii * 128;        // 0..511
            const int r = i >> 4;                // 0..31
            const int c = i & 15;
            const uint32_t so = (uint32_t)(r * FA_STRIDE + c * 16);
            const size_t go = kvBase + (size_t)(k0 + r) * HDIM + c * 8;
            CP_ASYNC16(tb + 0 * FA_KVTILE + so, (const char*)(k + go));
            CP_ASYNC16(tb + 1 * FA_KVTILE + so, (const char*)(v + go));
        }
        CP_ASYNC_COMMIT();
    };
    load_stage(0, 0);
    load_stage(1, 32);

    // Q fragments -> registers (wait for Q group; 2 KV groups may pend)
    const uint32_t aOff = (uint32_t)((16 * wid + (lane & 15)) * FA_STRIDE + (lane >> 4) * 16);
    uint32_t qA[8][4];
    CP_ASYNC_WAIT(2);
    __syncthreads();
    #pragma unroll
    for (int kd = 0; kd < 8; kd++)
        ldsm4(qA[kd], sQ + aOff + kd * 32);

    float O[16][4];
    #pragma unroll
    for (int i = 0; i < 16; i++)
        #pragma unroll
        for (int j = 0; j < 4; j++) O[i][j] = 0.0f;
    float m0 = -1e30f, m1 = -1e30f, l0 = 0.0f, l1 = 0.0f;

    const uint32_t bOff = (uint32_t)(((lane & 7) + ((lane >> 4) & 1) * 8) * FA_STRIDE
                                     + ((lane >> 3) & 1) * 16);
    const uint32_t vOff = (uint32_t)(((lane & 7) + ((lane >> 3) & 1) * 8) * FA_STRIDE
                                     + ((lane >> 4) & 1) * 16);
    const float* mrow = mask + (size_t)b * SSEQ;
    const float LOG2E  = 1.4426950408889634f;
    const float scale2 = 0.08838834764831845f * LOG2E;   // (1/sqrt(128))*log2(e)

    for (int c = 0; c < 64; c++) {
        if (c + 1 < 64) { CP_ASYNC_WAIT(1); } else { CP_ASYNC_WAIT(0); }
        __syncthreads();
        if (c + 2 < 64) load_stage((c + 2) % 3, (c + 2) * 32);

        const uint32_t tb = sStg + (c % 3) * FA_STAGE;
        const int k0 = c * 32;

        float S[4][4];
        #pragma unroll
        for (int i = 0; i < 4; i++)
            #pragma unroll
            for (int j = 0; j < 4; j++) S[i][j] = 0.0f;

        #pragma unroll
        for (int kd = 0; kd < 8; kd++) {
            #pragma unroll
            for (int np = 0; np < 2; np++) {
                uint32_t bH[4];
                ldsm4(bH, tb + 0 * FA_KVTILE + bOff + np * (16 * FA_STRIDE) + kd * 32);
                mma16816(S[2 * np],     qA[kd], bH[0], bH[1]);
                mma16816(S[2 * np + 1], qA[kd], bH[2], bH[3]);
            }
        }

        // ---- scale + mask (log2 domain)
        #pragma unroll
        for (int nt = 0; nt < 4; nt++) {
            const float2 mv = *reinterpret_cast<const float2*>(mrow + k0 + nt * 8 + 2 * tig);
            const float mx2 = mv.x * LOG2E;
            const float my2 = mv.y * LOG2E;
            S[nt][0] = fmaf(S[nt][0], scale2, mx2);
            S[nt][1] = fmaf(S[nt][1], scale2, my2);
            S[nt][2] = fmaf(S[nt][2], scale2, mx2);
            S[nt][3] = fmaf(S[nt][3], scale2, my2);
        }

        float mx0 = -1e30f, mx1 = -1e30f;
        #pragma unroll
        for (int nt = 0; nt < 4; nt++) {
            mx0 = fmaxf(mx0, fmaxf(S[nt][0], S[nt][1]));
            mx1 = fmaxf(mx1, fmaxf(S[nt][2], S[nt][3]));
        }
        mx0 = fmaxf(mx0, __shfl_xor_sync(0xFFFFFFFFu, mx0, 1));
        mx0 = fmaxf(mx0, __shfl_xor_sync(0xFFFFFFFFu, mx0, 2));
        mx1 = fmaxf(mx1, __shfl_xor_sync(0xFFFFFFFFu, mx1, 1));
        mx1 = fmaxf(mx1, __shfl_xor_sync(0xFFFFFFFFu, mx1, 2));

        const float nm0 = fmaxf(m0, mx0);
        const float nm1 = fmaxf(m1, mx1);
        const float ef0 = fast_exp2(m0 - nm0);
        const float ef1 = fast_exp2(m1 - nm1);

        float rs0 = 0.0f, rs1 = 0.0f;
        #pragma unroll
        for (int nt = 0; nt < 4; nt++) {
            S[nt][0] = fast_exp2(S[nt][0] - nm0);
            S[nt][1] = fast_exp2(S[nt][1] - nm0);
            S[nt][2] = fast_exp2(S[nt][2] - nm1);
            S[nt][3] = fast_exp2(S[nt][3] - nm1);
            rs0 += S[nt][0] + S[nt][1];
            rs1 += S[nt][2] + S[nt][3];
        }
        rs0 += __shfl_xor_sync(0xFFFFFFFFu, rs0, 1);
        rs0 += __shfl_xor_sync(0xFFFFFFFFu, rs0, 2);
        rs1 += __shfl_xor_sync(0xFFFFFFFFu, rs1, 1);
        rs1 += __shfl_xor_sync(0xFFFFFFFFu, rs1, 2);

        l0 = l0 * ef0 + rs0;
        l1 = l1 * ef1 + rs1;
        m0 = nm0; m1 = nm1;

        #pragma unroll
        for (int nt = 0; nt < 16; nt++) {
            O[nt][0] *= ef0; O[nt][1] *= ef0;
            O[nt][2] *= ef1; O[nt][3] *= ef1;
        }

        // ---- P (single fp16) @ V (single fp16)
        #pragma unroll
        for (int ks = 0; ks < 2; ks++) {
            uint32_t paH[4];
            #pragma unroll
            for (int qq = 0; qq < 2; qq++) {
                const float* s4 = S[2 * ks + qq];
                paH[qq * 2 + 0] = pack_half2(s4[0], s4[1]);
                paH[qq * 2 + 1] = pack_half2(s4[2], s4[3]);
            }
            #pragma unroll
            for (int ntp = 0; ntp < 8; ntp++) {
                uint32_t vH[4];
                ldsm4t(vH, tb + 1 * FA_KVTILE + vOff + ks * (16 * FA_STRIDE) + ntp * 32);
                mma16816(O[2 * ntp],     paH, vH[0], vH[1]);
                mma16816(O[2 * ntp + 1], paH, vH[2], vH[3]);
            }
        }
    }

    const float inv0 = 1.0f / l0;
    const float inv1 = 1.0f / l1;
    const int r0 = q0 + 16 * wid + gid;
    const int r1 = r0 + 8;
    #pragma unroll
    for (int nt = 0; nt < 16; nt++) {
        const int d = h * HDIM + nt * 8 + 2 * tig;
        const size_t i0 = ((size_t)b * SSEQ + r0) * HIDDEN + d;
        const size_t i1 = ((size_t)b * SSEQ + r1) * HIDDEN + d;
        __half2 t0, t1;
        t0.x = __float2half_rn(O[nt][0] * inv0);
        t0.y = __float2half_rn(O[nt][1] * inv0);
        t1.x = __float2half_rn(O[nt][2] * inv1);
        t1.y = __float2half_rn(O[nt][3] * inv1);
        *reinterpret_cast<__half2*>(&ao[i0]) = t0;
        *reinterpret_cast<__half2*>(&ao[i1]) = t1;
    }
}

// ===================== fp32 -> fp16 conversions =============================
__global__ void __launch_bounds__(256)
cvt_fp16(const float* __restrict__ in, __half* __restrict__ out, int n4)
{
    const int i = blockIdx.x * 256 + threadIdx.x;
    if (i >= n4) return;
    const float4 v = reinterpret_cast<const float4*>(in)[i];
    union { __half b[4]; uint2 u; } H;
    H.b[0] = __float2half_rn(v.x);
    H.b[1] = __float2half_rn(v.y);
    H.b[2] = __float2half_rn(v.z);
    H.b[3] = __float2half_rn(v.w);
    reinterpret_cast<uint2*>(out)[i] = H.u;
}

// 4 weight matrices in one launch: blockIdx.y selects Wq/Wk/Wv/Wo.
__global__ void __launch_bounds__(256)
cvt_fp16_w4(const float* __restrict__ w0, const float* __restrict__ w1,
            const float* __restrict__ w2, const float* __restrict__ w3,
            __half* __restrict__ w3o, __half* __restrict__ woo, int n4)
{
    const int i = blockIdx.x * 256 + threadIdx.x;
    if (i >= n4) return;
    const int p = blockIdx.y;
    const float* in = (p == 0) ? w0 : (p == 1) ? w1 : (p == 2) ? w2 : w3;
    const size_t wOff = (size_t)HIDDEN * HIDDEN / 4;   // in uint2 units
    __half* dst;
    size_t o;
    if (p < 3) { dst = w3o; o = (size_t)p * wOff; }
    else       { dst = woo; o = 0; }

    const float4 v = reinterpret_cast<const float4*>(in)[i];
    union { __half b[4]; uint2 u; } H;
    H.b[0] = __float2half_rn(v.x);
    H.b[1] = __float2half_rn(v.y);
    H.b[2] = __float2half_rn(v.z);
    H.b[3] = __float2half_rn(v.w);
    reinterpret_cast<uint2*>(dst)[o + i] = H.u;
}

// bias concat: [bq | bk | bv]
__global__ void __launch_bounds__(256)
concat_bias(const float* __restrict__ a, const float* __restrict__ b,
            const float* __restrict__ c, float* __restrict__ o)
{
    const int i = blockIdx.x * 256 + threadIdx.x;
    if (i < HIDDEN)          o[i] = a[i];
    else if (i < 2 * HIDDEN) o[i] = b[i - HIDDEN];
    else if (i < 3 * HIDDEN) o[i] = c[i - 2 * HIDDEN];
}

// ---------------------------------------------------------------------------
extern "C" void kernel_launch(void* const* d_in, const int* in_sizes, int n_in,
                              void* d_out, int out_size)
{
    (void)in_sizes; (void)n_in; (void)out_size;
    const float* x    = (const float*)d_in[0];
    const float* mask = (const float*)d_in[1];
    const float* Wq   = (const float*)d_in[2];
    const float* bq   = (const float*)d_in[3];
    const float* Wk   = (const float*)d_in[4];
    const float* bk   = (const float*)d_in[5];
    const float* Wv   = (const float*)d_in[6];
    const float* bv   = (const float*)d_in[7];
    const float* Wo   = (const float*)d_in[8];
    const float* bo   = (const float*)d_in[9];
    float* out = (float*)d_out;

    __half *xs, *w3, *wo, *qs, *ks, *vs, *aos;
    float* b3;
    cudaGetSymbolAddress((void**)&xs,  g_x);
    cudaGetSymbolAddress((void**)&w3,  g_w3);
    cudaGetSymbolAddress((void**)&wo,  g_wo);
    cudaGetSymbolAddress((void**)&b3,  g_b3);
    cudaGetSymbolAddress((void**)&qs,  g_q);
    cudaGetSymbolAddress((void**)&ks,  g_k);
    cudaGetSymbolAddress((void**)&vs,  g_v);
    cudaGetSymbolAddress((void**)&aos, g_ao);

    cudaFuncSetAttribute(tgemm_nt, cudaFuncAttributeMaxDynamicSharedMemorySize,
                         TG_SMEM);
    cudaFuncSetAttribute(fa_kernel, cudaFuncAttributeMaxDynamicSharedMemorySize,
                         FA_SMEM);

    // ---- conversions
    const int nX4 = (MROWS * HIDDEN) / 4;
    const int nW4 = (HIDDEN * HIDDEN) / 4;
    cvt_fp16<<<nX4 / 256, 256>>>(x, xs, nX4);
    cvt_fp16_w4<<<dim3(nW4 / 256, 4), 256>>>(Wq, Wk, Wv, Wo, w3, wo, nW4);
    concat_bias<<<(3 * HIDDEN) / 256, 256>>>(bq, bk, bv, b3);

    // ---- fused QKV projection -> q, k, v single fp16 [B,H,S,D]
    const dim3 gQKV(3 * HIDDEN / 128, MROWS / 128, 1);   // (48, 32)
    tgemm_nt<<<gQKV, 128, TG_SMEM>>>(xs, w3, b3, HIDDEN, 3 * HIDDEN, 1,
                                     nullptr, qs, ks, vs);

    // ---- fused attention -> AO single fp16 [B,S,HIDDEN]
    const dim3 gFA(SSEQ / 64, BH, 1);   // (32, 32) = 1024 CTAs
    fa_kernel<<<gFA, 128, FA_SMEM>>>(qs, ks, vs, mask, aos);

    // ---- output projection (+bias) -> d_out
    const dim3 gO(HIDDEN / 128, MROWS / 128, 1);
    tgemm_nt<<<gO, 128, TG_SMEM>>>(aos, wo, bo, HIDDEN, HIDDEN, 0,
                                   out, nullptr, nullptr, nullptr);
}